// round 3
// baseline (speedup 1.0000x reference)
#include <cuda_runtime.h>
#include <cstdint>
#include <cstddef>

// Problem constants
constexpr int Tn  = 2048;
constexpr int Cn  = 2048;
constexpr int Hh  = 32;
constexpr int Ssz = 64;
constexpr int HKV = 8;
constexpr size_t TC = (size_t)Tn * Cn;          // 4194304

// Scratch layout (single __device__ array; no allocations allowed)
constexpr size_t OFF_SX   = 0;
constexpr size_t OFF_XXX  = OFF_SX   + TC;
constexpr size_t OFF_MAA  = OFF_XXX  + TC;                // 5*2048
constexpr size_t OFF_MBUF = OFF_MAA  + 5 * 2048;          // T x 160
constexpr size_t OFF_XB   = OFF_MBUF + (size_t)Tn * 160;  // 5 x T x C
constexpr size_t OFF_R    = OFF_XB   + 5 * TC;
constexpr size_t OFF_K    = OFF_R    + TC;                // T x 512
constexpr size_t OFF_V    = OFF_K    + (size_t)Tn * 512;
constexpr size_t OFF_D1   = OFF_V    + (size_t)Tn * 512;  // T x 64
constexpr size_t OFF_EW   = OFF_D1   + (size_t)Tn * 64;
constexpr size_t OFF_KK   = OFF_EW   + TC;
constexpr size_t OFF_G    = OFF_KK   + TC;
constexpr size_t OFF_OS   = OFF_G    + TC;
constexpr size_t OFF_SF   = OFF_OS   + TC;                // 32*64*64
constexpr size_t SCRATCH_TOTAL = OFF_SF + (size_t)Hh * Ssz * Ssz;

__device__ float g_scratch[SCRATCH_TOTAL];

// ---------------------------------------------------------------------------
// prep: sx = (prev token | state0, zeroed at starts) - x ; xxx = x + sx*maa_x
// also packs the 5 per-branch maa vectors into one [5][C] buffer
// ---------------------------------------------------------------------------
__global__ void prep_kernel(const float* __restrict__ x,
                            const float* __restrict__ state,
                            const unsigned char* __restrict__ ns,
                            const float* __restrict__ tmx,
                            const float* __restrict__ tmr,
                            const float* __restrict__ tmk,
                            const float* __restrict__ tmv,
                            const float* __restrict__ tmw,
                            const float* __restrict__ tmg,
                            float* __restrict__ sx,
                            float* __restrict__ xxx,
                            float* __restrict__ maacat) {
    size_t idx = (size_t)blockIdx.x * blockDim.x + threadIdx.x;
    if (idx < TC) {
        int t = (int)(idx >> 11);
        int c = (int)(idx & 2047);
        float prev = (t == 0) ? state[c] : x[idx - Cn];
        if (ns[t]) prev = 0.0f;
        float xv = x[idx];
        float sxv = prev - xv;
        sx[idx] = sxv;
        xxx[idx] = xv + sxv * tmx[c];
    }
    if (idx < 5 * 2048) {
        int n = (int)(idx >> 11);
        int c = (int)(idx & 2047);
        const float* p = (n == 0) ? tmr : (n == 1) ? tmk : (n == 2) ? tmv
                       : (n == 3) ? tmw : tmg;
        maacat[idx] = p[c];
    }
}

// ---------------------------------------------------------------------------
// Generic fp32 GEMM: C = epi(A[M,K] @ B[K,N]); 128x128 tile, BK=8, 256 thr
// EPI: 0 plain | 1 tanh | 2 sigmoid | 3 token-shift-mix branch (grid.z = 5)
//      4 decay (-> ew & scaled k) | 5 plain with A-side elementwise gate
// ---------------------------------------------------------------------------
template <int EPI>
__global__ __launch_bounds__(256)
void gemm_k(const float* __restrict__ A, int lda,
            const float* __restrict__ B, int ldb,
            float* __restrict__ Cout, int ldc,
            int M, int N, int K,
            const float* __restrict__ bias,
            const float* __restrict__ amul,
            float* __restrict__ out2,
            const float* __restrict__ kin,
            const float* __restrict__ xp,
            const float* __restrict__ sxp,
            const float* __restrict__ maap) {
    if (EPI == 3) {
        // per-branch offsets: A cols z*32, B rows z*32 (w2 is [5][32][C] contiguous),
        // output buffer z*T*C, maa vector z*C
        A    += blockIdx.z * 32;
        B    += (size_t)blockIdx.z * 32 * 2048;
        Cout += (size_t)blockIdx.z * (size_t)M * (size_t)ldc;
        maap += (size_t)blockIdx.z * 2048;
    }

    __shared__ float As[8][128];
    __shared__ float Bs[8][128];

    int tid = threadIdx.x;
    int tx = tid & 15;   // N-direction
    int ty = tid >> 4;   // M-direction
    int bx = blockIdx.x;
    int by = blockIdx.y;

    float acc[8][8];
#pragma unroll
    for (int i = 0; i < 8; i++)
#pragma unroll
        for (int j = 0; j < 8; j++) acc[i][j] = 0.0f;

    int ar = tid >> 1;          // 0..127
    int ac = (tid & 1) * 4;     // 0 or 4
    int br = tid >> 5;          // 0..7
    int bc = (tid & 31) * 4;    // 0..124

    for (int k0 = 0; k0 < K; k0 += 8) {
        // load A tile (transposed into SMEM)
        {
            const float* ap = A + (size_t)(by * 128 + ar) * lda + k0 + ac;
            float4 av = *(const float4*)ap;
            if (EPI == 5) {
                float4 mv = *(const float4*)(amul + (size_t)(by * 128 + ar) * lda + k0 + ac);
                av.x *= mv.x; av.y *= mv.y; av.z *= mv.z; av.w *= mv.w;
            }
            As[ac + 0][ar] = av.x;
            As[ac + 1][ar] = av.y;
            As[ac + 2][ar] = av.z;
            As[ac + 3][ar] = av.w;
        }
        // load B tile (zero-pad past N)
        {
            int col = bx * 128 + bc;
            const float* bp = B + (size_t)(k0 + br) * ldb + col;
#pragma unroll
            for (int j = 0; j < 4; j++)
                Bs[br][bc + j] = (col + j < N) ? bp[j] : 0.0f;
        }
        __syncthreads();

#pragma unroll
        for (int kk = 0; kk < 8; kk++) {
            float a[8], b[8];
#pragma unroll
            for (int i = 0; i < 8; i++) a[i] = As[kk][ty * 8 + i];
#pragma unroll
            for (int j = 0; j < 8; j++) b[j] = Bs[kk][tx * 8 + j];
#pragma unroll
            for (int i = 0; i < 8; i++)
#pragma unroll
                for (int j = 0; j < 8; j++) acc[i][j] += a[i] * b[j];
        }
        __syncthreads();
    }

    int row0 = by * 128 + ty * 8;
    int col0 = bx * 128 + tx * 8;
#pragma unroll
    for (int i = 0; i < 8; i++) {
        int row = row0 + i;
#pragma unroll
        for (int j = 0; j < 8; j++) {
            int col = col0 + j;
            if (col >= N) continue;
            float v = acc[i][j];
            size_t oidx = (size_t)row * ldc + col;
            if (EPI == 0 || EPI == 5) {
                Cout[oidx] = v;
            } else if (EPI == 1) {
                Cout[oidx] = tanhf(v);
            } else if (EPI == 2) {
                Cout[oidx] = 1.0f / (1.0f + expf(-v));
            } else if (EPI == 3) {
                size_t idx = (size_t)row * 2048 + col;
                Cout[oidx] = xp[idx] + sxp[idx] * (maap[col] + v);
            } else if (EPI == 4) {
                float dec = v + bias[col];
                float lw = fmaxf(-expf(dec), -5.0f);
                float ew = expf(lw);
                Cout[oidx] = ew;  // exp(log_w)
                // k (grouped, H_KV=8) repeated 4x over heads, scaled by (1-ew)
                float kvv = kin[(size_t)row * 512 + (col >> 8) * 64 + (col & 63)];
                out2[oidx] = kvv * (1.0f - ew);
            }
        }
    }
}

// ---------------------------------------------------------------------------
// Sequential scan over T. Grid: (4 v-chunks, 32 heads), 256 threads.
// Thread (vl = tid/16, kg = tid%16) owns state s[k=kg*4..kg*4+3][v=vs+vl].
// ---------------------------------------------------------------------------
__global__ __launch_bounds__(256)
void scan_kernel(const float* __restrict__ r,
                 const float* __restrict__ kk,
                 const float* __restrict__ ew,
                 const float* __restrict__ v,
                 const unsigned char* __restrict__ ns,
                 const float* __restrict__ state,
                 float* __restrict__ out,
                 float* __restrict__ sfin) {
    int h = blockIdx.y;
    int vs = blockIdx.x * 16;
    int tid = threadIdx.x;
    int vl = tid >> 4;
    int kg = tid & 15;
    int vcol = vs + vl;
    int hv4 = (h >> 2) * 64;  // kv-head column base

    float s[4];
#pragma unroll
    for (int i = 0; i < 4; i++) {
        int krow = kg * 4 + i;
        s[i] = state[2048 + h * 4096 + krow * 64 + vcol];
    }

    __shared__ float rs[2][64], ks[2][64], ws[2][64], vsd[2][16];

    for (int t = 0; t < Tn; t++) {
        int b = t & 1;
        size_t base = (size_t)t * 2048 + h * 64;
        if (tid < 64)       rs[b][tid]        = r[base + tid];
        else if (tid < 128) ks[b][tid - 64]   = kk[base + (tid - 64)];
        else if (tid < 192) ws[b][tid - 128]  = ew[base + (tid - 128)];
        else if (tid < 208) vsd[b][tid - 192] = v[(size_t)t * 512 + hv4 + vs + (tid - 192)];
        __syncthreads();

        if (ns[t]) { s[0] = 0.f; s[1] = 0.f; s[2] = 0.f; s[3] = 0.f; }
        float vv = vsd[b][vl];
        float po = 0.0f;
#pragma unroll
        for (int i = 0; i < 4; i++) {
            int krow = kg * 4 + i;
            s[i] = s[i] * ws[b][krow] + ks[b][krow] * vv;
            po += rs[b][krow] * s[i];
        }
        po += __shfl_down_sync(0xffffffffu, po, 8, 16);
        po += __shfl_down_sync(0xffffffffu, po, 4, 16);
        po += __shfl_down_sync(0xffffffffu, po, 2, 16);
        po += __shfl_down_sync(0xffffffffu, po, 1, 16);
        if (kg == 0) out[base + vcol] = po;
    }

#pragma unroll
    for (int i = 0; i < 4; i++) {
        int krow = kg * 4 + i;
        sfin[h * 4096 + krow * 64 + vcol] = s[i];
    }
}

// ---------------------------------------------------------------------------
// tail: append new_state (row0 = x[length-1], rows 1..64 = final scan state)
// ---------------------------------------------------------------------------
__global__ void tail_kernel(const float* __restrict__ x,
                            const int* __restrict__ lenp,
                            const float* __restrict__ sfin,
                            float* __restrict__ out) {
    int idx = blockIdx.x * blockDim.x + threadIdx.x;
    if (idx >= 65 * 2048) return;
    int len = *lenp;
    float v;
    if (idx < 2048) v = x[(size_t)(len - 1) * 2048 + idx];
    else            v = sfin[idx - 2048];
    out[TC + idx] = v;
}

// ---------------------------------------------------------------------------
extern "C" void kernel_launch(void* const* d_in, const int* in_sizes, int n_in,
                              void* d_out, int out_size) {
    (void)in_sizes; (void)n_in;
    const float* x     = (const float*)d_in[0];
    const float* state = (const float*)d_in[1];
    const unsigned char* ns = (const unsigned char*)d_in[2];
    const int* lenp    = (const int*)d_in[3];
    const float* tmx   = (const float*)d_in[4];
    const float* tmr   = (const float*)d_in[5];
    const float* tmk   = (const float*)d_in[6];
    const float* tmv   = (const float*)d_in[7];
    const float* tmw   = (const float*)d_in[8];
    const float* tmg   = (const float*)d_in[9];
    const float* w1    = (const float*)d_in[10];  // [C, 160]
    const float* w2    = (const float*)d_in[11];  // [5, 32, C]
    const float* tdec  = (const float*)d_in[12];  // [C]
    const float* tdw1  = (const float*)d_in[13];  // [C, 64]
    const float* tdw2  = (const float*)d_in[14];  // [64, C]
    const float* Wq    = (const float*)d_in[15];
    const float* Wk    = (const float*)d_in[16];
    const float* Wv    = (const float*)d_in[17];
    const float* Wg    = (const float*)d_in[18];
    const float* Wo    = (const float*)d_in[19];
    float* out = (float*)d_out;

    float* S = nullptr;
    cudaGetSymbolAddress((void**)&S, g_scratch);

    float* sx    = S + OFF_SX;
    float* xxx   = S + OFF_XXX;
    float* maa   = S + OFF_MAA;
    float* mbuf  = S + OFF_MBUF;
    float* xb    = S + OFF_XB;
    float* rbuf  = S + OFF_R;
    float* kraw  = S + OFF_K;
    float* vbuf  = S + OFF_V;
    float* d1    = S + OFF_D1;
    float* ewb   = S + OFF_EW;
    float* kkb   = S + OFF_KK;
    float* gbuf  = S + OFF_G;
    float* oscan = S + OFF_OS;
    float* sfin  = S + OFF_SF;

    // 1. token shift + maa pack
    prep_kernel<<<(unsigned)((TC + 255) / 256), 256>>>(
        x, state, ns, tmx, tmr, tmk, tmv, tmw, tmg, sx, xxx, maa);

    // 2. m = tanh(xxx @ w1)   [T,160]
    gemm_k<1><<<dim3(2, 16), 256>>>(xxx, 2048, w1, 160, mbuf, 160,
                                    Tn, 160, 2048,
                                    nullptr, nullptr, nullptr, nullptr,
                                    nullptr, nullptr, nullptr);

    // 3. 5 branches: xb[z] = x + sx*(maa_z + m_z @ w2_z)   [5,T,C]
    gemm_k<3><<<dim3(16, 16, 5), 256>>>(mbuf, 160, w2, 2048, xb, 2048,
                                        Tn, 2048, 32,
                                        nullptr, nullptr, nullptr, nullptr,
                                        x, sx, maa);

    // 4. r = xr @ Wq   [T,2048]
    gemm_k<0><<<dim3(16, 16), 256>>>(xb + 0 * TC, 2048, Wq, 2048, rbuf, 2048,
                                     Tn, 2048, 2048,
                                     nullptr, nullptr, nullptr, nullptr,
                                     nullptr, nullptr, nullptr);
    // 5. k = xk @ Wk   [T,512]
    gemm_k<0><<<dim3(4, 16), 256>>>(xb + 1 * TC, 2048, Wk, 512, kraw, 512,
                                    Tn, 512, 2048,
                                    nullptr, nullptr, nullptr, nullptr,
                                    nullptr, nullptr, nullptr);
    // 6. v = xv @ Wv   [T,512]
    gemm_k<0><<<dim3(4, 16), 256>>>(xb + 2 * TC, 2048, Wv, 512, vbuf, 512,
                                    Tn, 512, 2048,
                                    nullptr, nullptr, nullptr, nullptr,
                                    nullptr, nullptr, nullptr);
    // 7. d1 = tanh(xw @ tdw1)   [T,64]
    gemm_k<1><<<dim3(1, 16), 256>>>(xb + 3 * TC, 2048, tdw1, 64, d1, 64,
                                    Tn, 64, 2048,
                                    nullptr, nullptr, nullptr, nullptr,
                                    nullptr, nullptr, nullptr);
    // 8. dec = d1 @ tdw2 + time_decay -> ew = exp(log_w), kk = k_rep*(1-ew)
    gemm_k<4><<<dim3(16, 16), 256>>>(d1, 64, tdw2, 2048, ewb, 2048,
                                     Tn, 2048, 64,
                                     tdec, nullptr, kkb, kraw,
                                     nullptr, nullptr, nullptr);
    // 9. g = sigmoid(xg @ Wg)   [T,2048]
    gemm_k<2><<<dim3(16, 16), 256>>>(xb + 4 * TC, 2048, Wg, 2048, gbuf, 2048,
                                     Tn, 2048, 2048,
                                     nullptr, nullptr, nullptr, nullptr,
                                     nullptr, nullptr, nullptr);

    // 10. sequential scan
    scan_kernel<<<dim3(4, 32), 256>>>(rbuf, kkb, ewb, vbuf, ns, state,
                                      oscan, sfin);

    // 11. out = (oscan * g) @ Wo
    gemm_k<5><<<dim3(16, 16), 256>>>(oscan, 2048, Wo, 2048, out, 2048,
                                     Tn, 2048, 2048,
                                     nullptr, gbuf, nullptr, nullptr,
                                     nullptr, nullptr, nullptr);

    // 12. new_state, if the output buffer includes it
    if ((size_t)out_size >= TC + 65 * 2048) {
        tail_kernel<<<(65 * 2048 + 255) / 256, 256>>>(x, lenp, sfin, out);
    }
}

// round 7
// speedup vs baseline: 1.3257x; 1.3257x over previous
#include <cuda_runtime.h>
#include <cuda_bf16.h>
#include <cstdint>
#include <cstddef>

constexpr int Tn = 2048;
constexpr size_t TC = (size_t)Tn * 2048;  // 4194304

// ---------------- scratch layout (float units) ----------------
constexpr size_t OFF_SX   = 0;                         // TC
constexpr size_t OFF_MAA  = OFF_SX   + TC;             // 5*2048
constexpr size_t OFF_MBUF = OFF_MAA  + 5 * 2048;       // T*160
constexpr size_t OFF_D1   = OFF_MBUF + (size_t)Tn*160; // T*64
constexpr size_t OFF_EW   = OFF_D1   + (size_t)Tn*64;  // TC
constexpr size_t OFF_KK   = OFF_EW   + TC;             // TC
constexpr size_t OFF_G    = OFF_KK   + TC;             // TC
constexpr size_t OFF_R    = OFF_G    + TC;             // TC
constexpr size_t OFF_KR   = OFF_R    + TC;             // T*512
constexpr size_t OFF_V    = OFF_KR   + (size_t)Tn*512; // T*512
constexpr size_t OFF_SF   = OFF_V    + (size_t)Tn*512; // 131072
// bf16 regions (float units = bf16 count / 2)
constexpr size_t OFF_XXH = OFF_SF  + 131072;
constexpr size_t OFF_XXL = OFF_XXH + TC/2;
constexpr size_t OFF_XBH = OFF_XXL + TC/2;          // 5*TC bf16
constexpr size_t OFF_XBL = OFF_XBH + 5*TC/2;
constexpr size_t OFF_OGH = OFF_XBL + 5*TC/2;
constexpr size_t OFF_OGL = OFF_OGH + TC/2;
constexpr size_t OFF_WQH = OFF_OGL + TC/2;
constexpr size_t OFF_WQL = OFF_WQH + TC/2;
constexpr size_t OFF_WGH = OFF_WQL + TC/2;
constexpr size_t OFF_WGL = OFF_WGH + TC/2;
constexpr size_t OFF_WOH = OFF_WGL + TC/2;
constexpr size_t OFF_WOL = OFF_WOH + TC/2;
constexpr size_t OFF_WKH = OFF_WOL + TC/2;
constexpr size_t OFF_WKL = OFF_WKH + (size_t)512*1024;
constexpr size_t OFF_WVH = OFF_WKL + (size_t)512*1024;
constexpr size_t OFF_WVL = OFF_WVH + (size_t)512*1024;
constexpr size_t OFF_W1H = OFF_WVL + (size_t)512*1024;
constexpr size_t OFF_W1L = OFF_W1H + (size_t)160*1024;
constexpr size_t OFF_TDH = OFF_W1L + (size_t)160*1024;
constexpr size_t OFF_TDL = OFF_TDH + (size_t)64*1024;
constexpr size_t SCRATCH_TOTAL = OFF_TDL + (size_t)64*1024;

__device__ float g_scratch[SCRATCH_TOTAL];

// ---------------- PTX helpers (standard ISA only — no 'a'-features) --------
__device__ __forceinline__ uint32_t smem_u32(const void* p) {
    uint32_t a;
    asm("{ .reg .u64 t; cvta.to.shared.u64 t, %1; cvt.u32.u64 %0, t; }" : "=r"(a) : "l"(p));
    return a;
}
__device__ __forceinline__ void ldsm4(uint32_t& r0, uint32_t& r1, uint32_t& r2,
                                      uint32_t& r3, uint32_t a) {
    asm volatile("ldmatrix.sync.aligned.m8n8.x4.shared.b16 {%0,%1,%2,%3}, [%4];"
        : "=r"(r0), "=r"(r1), "=r"(r2), "=r"(r3) : "r"(a));
}
__device__ __forceinline__ void mma16816(float* c, const uint32_t* a, const uint32_t* b) {
    asm volatile("mma.sync.aligned.m16n8k16.row.col.f32.bf16.bf16.f32 "
        "{%0,%1,%2,%3}, {%4,%5,%6,%7}, {%8,%9}, {%0,%1,%2,%3};"
        : "+f"(c[0]), "+f"(c[1]), "+f"(c[2]), "+f"(c[3])
        : "r"(a[0]), "r"(a[1]), "r"(a[2]), "r"(a[3]), "r"(b[0]), "r"(b[1]));
}
#define CP_ASYNC(dst, src, sz) \
    asm volatile("cp.async.cg.shared.global [%0], [%1], 16, %2;" \
        :: "r"(dst), "l"(src), "r"(sz))
#define CP_COMMIT() asm volatile("cp.async.commit_group;" ::: "memory")
#define CP_WAIT(n)  asm volatile("cp.async.wait_group %0;" :: "n"(n) : "memory")

// ---------------- prep ----------------
__global__ void prep_kernel(const float* __restrict__ x, const float* __restrict__ state,
                            const unsigned char* __restrict__ ns,
                            const float* __restrict__ tmx,
                            const float* __restrict__ tmr, const float* __restrict__ tmk,
                            const float* __restrict__ tmv, const float* __restrict__ tmw,
                            const float* __restrict__ tmg,
                            float* __restrict__ sx,
                            __nv_bfloat16* __restrict__ xxh, __nv_bfloat16* __restrict__ xxl,
                            float* __restrict__ maacat) {
    size_t idx = (size_t)blockIdx.x * blockDim.x + threadIdx.x;
    if (idx < TC) {
        int t = (int)(idx >> 11), c = (int)(idx & 2047);
        float prev = (t == 0) ? state[c] : x[idx - 2048];
        if (ns[t]) prev = 0.0f;
        float xv = x[idx];
        float sxv = prev - xv;
        sx[idx] = sxv;
        float xxx = xv + sxv * tmx[c];
        __nv_bfloat16 h = __float2bfloat16(xxx);
        xxh[idx] = h;
        xxl[idx] = __float2bfloat16(xxx - __bfloat162float(h));
    }
    if (idx < 5 * 2048) {
        int n = (int)(idx >> 11), c = (int)(idx & 2047);
        const float* p = (n == 0) ? tmr : (n == 1) ? tmk : (n == 2) ? tmv
                       : (n == 3) ? tmw : tmg;
        maacat[idx] = p[c];
    }
}

// ---------------- transpose+split: fp32 [2048, N] -> bf16 hi/lo [N, 2048] ----
__global__ void tsplit_kernel(const float* __restrict__ src,
                              __nv_bfloat16* __restrict__ dh,
                              __nv_bfloat16* __restrict__ dl, int N) {
    __shared__ float smt[32][33];
    int n0 = blockIdx.x * 32, k0 = blockIdx.y * 32;
    int tx = threadIdx.x, ty = threadIdx.y;
#pragma unroll
    for (int r = 0; r < 4; r++)
        smt[ty + r * 8][tx] = src[(size_t)(k0 + ty + r * 8) * N + n0 + tx];
    __syncthreads();
#pragma unroll
    for (int r = 0; r < 4; r++) {
        float v = smt[tx][ty + r * 8];
        __nv_bfloat16 h = __float2bfloat16(v);
        size_t o = (size_t)(n0 + ty + r * 8) * 2048 + k0 + tx;
        dh[o] = h;
        dl[o] = __float2bfloat16(v - __bfloat162float(h));
    }
}

// ===========================================================================
// HMMA bf16 hi/lo GEMM: C[2048, N] = epi(A @ B^T), K = 2048.
// A: [2048,2048] bf16 hi/lo row-major. B: [N,2048] bf16 hi/lo row-major.
// CTA tile 128x128, BK=32, 3-stage cp.async pipeline.
// 8 warps = 2(M) x 4(N); warp tile 64x32 = 4x4 m16n8k16.
// 3-term compensation: AhBh + AhBl + AlBh.
// ===========================================================================
constexpr int HM_STG  = 32768;          // per-stage: Ah|Al|Bh|Bl @ 8KB each
constexpr int HM_SMEM = 3 * HM_STG;     // 98304

template <int EPI>  // 0 plain, 1 tanh, 2 sigmoid
__global__ __launch_bounds__(256, 1)
void hm_gemm(const __nv_bfloat16* __restrict__ Ah, const __nv_bfloat16* __restrict__ Al,
             const __nv_bfloat16* __restrict__ Bh, const __nv_bfloat16* __restrict__ Bl,
             float* __restrict__ C, int N, int ldc) {
    extern __shared__ char sm[];
    uint32_t sb = smem_u32(sm);
    int tid = threadIdx.x, wid = tid >> 5, lane = tid & 31;
    int bx = blockIdx.x, by = blockIdx.y;
    int wm = wid >> 2, wn = wid & 3;

    auto load_stage = [&](int s, int kc) {
#pragma unroll
        for (int i = 0; i < 2; i++) {
            int chunk = tid + 256 * i;
            int row = chunk >> 2, c = chunk & 3;
            uint32_t dst = sb + s * HM_STG + row * 64 + ((c ^ ((row >> 1) & 3)) * 16);
            size_t goa = (size_t)(by * 128 + row) * 2048 + kc + c * 8;
            CP_ASYNC(dst,         Ah + goa, 16);
            CP_ASYNC(dst +  8192, Al + goa, 16);
            int gn = bx * 128 + row;
            int bsz = (gn < N) ? 16 : 0;
            size_t gob = (size_t)gn * 2048 + kc + c * 8;
            CP_ASYNC(dst + 16384, Bh + gob, bsz);
            CP_ASYNC(dst + 24576, Bl + gob, bsz);
        }
        CP_COMMIT();
    };

    load_stage(0, 0);
    load_stage(1, 32);

    float acc[4][4][4];
#pragma unroll
    for (int a = 0; a < 4; a++)
#pragma unroll
        for (int b = 0; b < 4; b++)
#pragma unroll
            for (int d = 0; d < 4; d++) acc[a][b][d] = 0.0f;

    const int arow = lane & 15;
    const int ahalf = lane >> 4;                         // k-half for A ldmatrix
    const int brow = (lane & 7) + ((lane >> 4) << 3);    // n within 16
    const int bhalf = (lane >> 3) & 1;                   // k-half for B ldmatrix

    for (int it = 0; it < 64; it++) {
        if (it + 2 < 64) load_stage((it + 2) % 3, (it + 2) * 32);
        if (it < 62)      CP_WAIT(2);
        else if (it == 62) CP_WAIT(1);
        else               CP_WAIT(0);
        __syncthreads();

        uint32_t sA = sb + (it % 3) * HM_STG;
        uint32_t sB = sA + 16384;
#pragma unroll
        for (int ks = 0; ks < 2; ks++) {
            uint32_t bh[2][4], bl[2][4];
#pragma unroll
            for (int p = 0; p < 2; p++) {
                int rn = wn * 32 + p * 16 + brow;
                int c = 2 * ks + bhalf;
                uint32_t addr = sB + rn * 64 + ((c ^ ((rn >> 1) & 3)) * 16);
                ldsm4(bh[p][0], bh[p][1], bh[p][2], bh[p][3], addr);
                ldsm4(bl[p][0], bl[p][1], bl[p][2], bl[p][3], addr + 8192);
            }
#pragma unroll
            for (int mt = 0; mt < 4; mt++) {
                int rm = wm * 64 + mt * 16 + arow;
                int c = 2 * ks + ahalf;
                uint32_t addr = sA + rm * 64 + ((c ^ ((rm >> 1) & 3)) * 16);
                uint32_t ah[4], al[4];
                ldsm4(ah[0], ah[1], ah[2], ah[3], addr);
                ldsm4(al[0], al[1], al[2], al[3], addr + 8192);
#pragma unroll
                for (int oc = 0; oc < 4; oc++) {
                    uint32_t bsh[2] = { bh[oc >> 1][(oc & 1) * 2], bh[oc >> 1][(oc & 1) * 2 + 1] };
                    uint32_t bsl[2] = { bl[oc >> 1][(oc & 1) * 2], bl[oc >> 1][(oc & 1) * 2 + 1] };
                    mma16816(acc[mt][oc], ah, bsh);
                    mma16816(acc[mt][oc], ah, bsl);
                    mma16816(acc[mt][oc], al, bsh);
                }
            }
        }
        __syncthreads();
    }

    // epilogue
    int r0 = by * 128 + wm * 64;
    int c0 = bx * 128 + wn * 32;
#pragma unroll
    for (int mt = 0; mt < 4; mt++) {
#pragma unroll
        for (int oc = 0; oc < 4; oc++) {
            int col = c0 + oc * 8 + (lane & 3) * 2;
            if (col >= N) continue;
            int row = r0 + mt * 16 + (lane >> 2);
            float v0 = acc[mt][oc][0], v1 = acc[mt][oc][1];
            float v2 = acc[mt][oc][2], v3 = acc[mt][oc][3];
            if (EPI == 1) { v0 = tanhf(v0); v1 = tanhf(v1); v2 = tanhf(v2); v3 = tanhf(v3); }
            else if (EPI == 2) {
                v0 = 1.f/(1.f+expf(-v0)); v1 = 1.f/(1.f+expf(-v1));
                v2 = 1.f/(1.f+expf(-v2)); v3 = 1.f/(1.f+expf(-v3));
            }
            float2 a = make_float2(v0, v1), b = make_float2(v2, v3);
            *(float2*)(C + (size_t)row * ldc + col) = a;
            *(float2*)(C + (size_t)(row + 8) * ldc + col) = b;
        }
    }
}

// ---------------- SIMT K=32: xb[z] = x + sx*(maa_z + mbuf_z @ w2_z) -> bf16
__global__ __launch_bounds__(256)
void gemm_branch(const float* __restrict__ A, const float* __restrict__ B,
                 const float* __restrict__ x, const float* __restrict__ sx,
                 const float* __restrict__ maa,
                 __nv_bfloat16* __restrict__ xbh, __nv_bfloat16* __restrict__ xbl) {
    int z = blockIdx.z;
    A += z * 32;
    B += (size_t)z * 32 * 2048;
    maa += (size_t)z * 2048;
    __nv_bfloat16* oh = xbh + (size_t)z * TC;
    __nv_bfloat16* ol = xbl + (size_t)z * TC;

    __shared__ float As[8][128], Bs[8][128];
    int tid = threadIdx.x, tx = tid & 15, ty = tid >> 4;
    int bx = blockIdx.x, by = blockIdx.y;
    float acc[8][8];
#pragma unroll
    for (int i = 0; i < 8; i++)
#pragma unroll
        for (int j = 0; j < 8; j++) acc[i][j] = 0.0f;
    int ar = tid >> 1, ac = (tid & 1) * 4, br = tid >> 5, bc = (tid & 31) * 4;
    for (int k0 = 0; k0 < 32; k0 += 8) {
        float4 av = *(const float4*)(A + (size_t)(by * 128 + ar) * 160 + k0 + ac);
        As[ac+0][ar] = av.x; As[ac+1][ar] = av.y; As[ac+2][ar] = av.z; As[ac+3][ar] = av.w;
        *(float4*)&Bs[br][bc] = *(const float4*)(B + (size_t)(k0 + br) * 2048 + bx * 128 + bc);
        __syncthreads();
#pragma unroll
        for (int kk = 0; kk < 8; kk++) {
            float a[8], b[8];
#pragma unroll
            for (int i = 0; i < 8; i++) a[i] = As[kk][ty * 8 + i];
#pragma unroll
            for (int j = 0; j < 8; j++) b[j] = Bs[kk][tx * 8 + j];
#pragma unroll
            for (int i = 0; i < 8; i++)
#pragma unroll
                for (int j = 0; j < 8; j++) acc[i][j] += a[i] * b[j];
        }
        __syncthreads();
    }
    int row0 = by * 128 + ty * 8, col0 = bx * 128 + tx * 8;
#pragma unroll
    for (int i = 0; i < 8; i++)
#pragma unroll
        for (int j = 0; j < 8; j++) {
            int col = col0 + j;
            size_t idx = (size_t)(row0 + i) * 2048 + col;
            float val = x[idx] + sx[idx] * (maa[col] + acc[i][j]);
            __nv_bfloat16 h = __float2bfloat16(val);
            oh[idx] = h;
            ol[idx] = __float2bfloat16(val - __bfloat162float(h));
        }
}

// ---------------- SIMT K=64: decay -> ew, kk ----------------
__global__ __launch_bounds__(256)
void gemm_decay(const float* __restrict__ A, const float* __restrict__ B,
                const float* __restrict__ bias, const float* __restrict__ kin,
                float* __restrict__ ewo, float* __restrict__ kko) {
    __shared__ float As[8][128], Bs[8][128];
    int tid = threadIdx.x, tx = tid & 15, ty = tid >> 4;
    int bx = blockIdx.x, by = blockIdx.y;
    float acc[8][8];
#pragma unroll
    for (int i = 0; i < 8; i++)
#pragma unroll
        for (int j = 0; j < 8; j++) acc[i][j] = 0.0f;
    int ar = tid >> 1, ac = (tid & 1) * 4, br = tid >> 5, bc = (tid & 31) * 4;
    for (int k0 = 0; k0 < 64; k0 += 8) {
        float4 av = *(const float4*)(A + (size_t)(by * 128 + ar) * 64 + k0 + ac);
        As[ac+0][ar] = av.x; As[ac+1][ar] = av.y; As[ac+2][ar] = av.z; As[ac+3][ar] = av.w;
        *(float4*)&Bs[br][bc] = *(const float4*)(B + (size_t)(k0 + br) * 2048 + bx * 128 + bc);
        __syncthreads();
#pragma unroll
        for (int kk = 0; kk < 8; kk++) {
            float a[8], b[8];
#pragma unroll
            for (int i = 0; i < 8; i++) a[i] = As[kk][ty * 8 + i];
#pragma unroll
            for (int j = 0; j < 8; j++) b[j] = Bs[kk][tx * 8 + j];
#pragma unroll
            for (int i = 0; i < 8; i++)
#pragma unroll
                for (int j = 0; j < 8; j++) acc[i][j] += a[i] * b[j];
        }
        __syncthreads();
    }
    int row0 = by * 128 + ty * 8, col0 = bx * 128 + tx * 8;
#pragma unroll
    for (int i = 0; i < 8; i++) {
        int row = row0 + i;
#pragma unroll
        for (int j = 0; j < 8; j++) {
            int col = col0 + j;
            float dec = acc[i][j] + bias[col];
            float lw = fmaxf(-expf(dec), -5.0f);
            float ew = expf(lw);
            size_t oidx = (size_t)row * 2048 + col;
            ewo[oidx] = ew;
            float kvv = kin[(size_t)row * 512 + (col >> 8) * 64 + (col & 63)];
            kko[oidx] = kvv * (1.0f - ew);
        }
    }
}

// ---------------- scan: prefetch + deferred reduce; og = (o*g) bf16 hi/lo --
__global__ __launch_bounds__(256)
void scan_kernel(const float* __restrict__ r, const float* __restrict__ kk,
                 const float* __restrict__ ew, const float* __restrict__ v,
                 const unsigned char* __restrict__ ns,
                 const float* __restrict__ state, const float* __restrict__ g,
                 __nv_bfloat16* __restrict__ ogh, __nv_bfloat16* __restrict__ ogl,
                 float* __restrict__ sfin) {
    int h = blockIdx.y, vs = blockIdx.x * 16;
    int tid = threadIdx.x, vl = tid >> 4, kg = tid & 15;
    int vcol = vs + vl, hv4 = (h >> 2) * 64;

    float s[4];
#pragma unroll
    for (int i = 0; i < 4; i++)
        s[i] = state[2048 + h * 4096 + (kg * 4 + i) * 64 + vcol];

    __shared__ float rs[2][64], ks[2][64], ws[2][64], vsd[2][16];
    __shared__ float pob[2][16][16];

    float reg = 0.0f;
    {
        size_t base = (size_t)h * 64;
        if (tid < 64)       reg = r[base + tid];
        else if (tid < 128) reg = kk[base + tid - 64];
        else if (tid < 192) reg = ew[base + tid - 128];
        else if (tid < 208) reg = v[hv4 + vs + tid - 192];
    }
    unsigned char nsr = ns[0];

    for (int t = 0; t < Tn; t++) {
        int b = t & 1;
        if (tid < 64)       rs[b][tid] = reg;
        else if (tid < 128) ks[b][tid - 64] = reg;
        else if (tid < 192) ws[b][tid - 128] = reg;
        else if (tid < 208) vsd[b][tid - 192] = reg;
        __syncthreads();

        unsigned char nsn = 0;
        if (t + 1 < Tn) {
            size_t base = (size_t)(t + 1) * 2048 + h * 64;
            if (tid < 64)       reg = r[base + tid];
            else if (tid < 128) reg = kk[base + tid - 64];
            else if (tid < 192) reg = ew[base + tid - 128];
            else if (tid < 208) reg = v[(size_t)(t + 1) * 512 + hv4 + vs + tid - 192];
            nsn = ns[t + 1];
        }

        if (t > 0 && kg == 0) {
            float acc = 0.0f;
#pragma unroll
            for (int i = 0; i < 16; i++) acc += pob[1 - b][i][vl];
            size_t ob = (size_t)(t - 1) * 2048 + h * 64 + vcol;
            float val = acc * g[ob];
            __nv_bfloat16 hh = __float2bfloat16(val);
            ogh[ob] = hh;
            ogl[ob] = __float2bfloat16(val - __bfloat162float(hh));
        }

        if (nsr) { s[0] = 0.f; s[1] = 0.f; s[2] = 0.f; s[3] = 0.f; }
        float vv = vsd[b][vl];
        float po = 0.0f;
#pragma unroll
        for (int i = 0; i < 4; i++) {
            int krow = kg * 4 + i;
            s[i] = s[i] * ws[b][krow] + ks[b][krow] * vv;
            po += rs[b][krow] * s[i];
        }
        pob[b][kg][vl] = po;
        nsr = nsn;
    }
    __syncthreads();
    if (kg == 0) {
        float acc = 0.0f;
#pragma unroll
        for (int i = 0; i < 16; i++) acc += pob[1][i][vl];
        size_t ob = (size_t)(Tn - 1) * 2048 + h * 64 + vcol;
        float val = acc * g[ob];
        __nv_bfloat16 hh = __float2bfloat16(val);
        ogh[ob] = hh;
        ogl[ob] = __float2bfloat16(val - __bfloat162float(hh));
    }
#pragma unroll
    for (int i = 0; i < 4; i++)
        sfin[h * 4096 + (kg * 4 + i) * 64 + vcol] = s[i];
}

// ---------------- tail ----------------
__global__ void tail_kernel(const float* __restrict__ x, const int* __restrict__ lenp,
                            const float* __restrict__ sfin, float* __restrict__ out) {
    int idx = blockIdx.x * blockDim.x + threadIdx.x;
    if (idx >= 65 * 2048) return;
    int len = *lenp;
    out[TC + idx] = (idx < 2048) ? x[(size_t)(len - 1) * 2048 + idx] : sfin[idx - 2048];
}

// ---------------------------------------------------------------------------
extern "C" void kernel_launch(void* const* d_in, const int* in_sizes, int n_in,
                              void* d_out, int out_size) {
    (void)in_sizes; (void)n_in;
    const float* x     = (const float*)d_in[0];
    const float* state = (const float*)d_in[1];
    const unsigned char* ns = (const unsigned char*)d_in[2];
    const int* lenp    = (const int*)d_in[3];
    const float* tmx   = (const float*)d_in[4];
    const float* tmr   = (const float*)d_in[5];
    const float* tmk   = (const float*)d_in[6];
    const float* tmv   = (const float*)d_in[7];
    const float* tmw   = (const float*)d_in[8];
    const float* tmg   = (const float*)d_in[9];
    const float* w1    = (const float*)d_in[10];
    const float* w2    = (const float*)d_in[11];
    const float* tdec  = (const float*)d_in[12];
    const float* tdw1  = (const float*)d_in[13];
    const float* tdw2  = (const float*)d_in[14];
    const float* Wq    = (const float*)d_in[15];
    const float* Wk    = (const float*)d_in[16];
    const float* Wv    = (const float*)d_in[17];
    const float* Wg    = (const float*)d_in[18];
    const float* Wo    = (const float*)d_in[19];
    float* out = (float*)d_out;

    float* S = nullptr;
    cudaGetSymbolAddress((void**)&S, g_scratch);
    auto bp = [&](size_t off) { return (__nv_bfloat16*)(S + off); };

    cudaFuncSetAttribute(hm_gemm<0>, cudaFuncAttributeMaxDynamicSharedMemorySize, HM_SMEM);
    cudaFuncSetAttribute(hm_gemm<1>, cudaFuncAttributeMaxDynamicSharedMemorySize, HM_SMEM);
    cudaFuncSetAttribute(hm_gemm<2>, cudaFuncAttributeMaxDynamicSharedMemorySize, HM_SMEM);

    // 1. prep
    prep_kernel<<<(unsigned)((TC + 255) / 256), 256>>>(
        x, state, ns, tmx, tmr, tmk, tmv, tmw, tmg,
        S + OFF_SX, bp(OFF_XXH), bp(OFF_XXL), S + OFF_MAA);

    // 2. weight transpose + split
    tsplit_kernel<<<dim3(64, 64), dim3(32, 8)>>>(Wq, bp(OFF_WQH), bp(OFF_WQL), 2048);
    tsplit_kernel<<<dim3(64, 64), dim3(32, 8)>>>(Wg, bp(OFF_WGH), bp(OFF_WGL), 2048);
    tsplit_kernel<<<dim3(64, 64), dim3(32, 8)>>>(Wo, bp(OFF_WOH), bp(OFF_WOL), 2048);
    tsplit_kernel<<<dim3(16, 64), dim3(32, 8)>>>(Wk, bp(OFF_WKH), bp(OFF_WKL), 512);
    tsplit_kernel<<<dim3(16, 64), dim3(32, 8)>>>(Wv, bp(OFF_WVH), bp(OFF_WVL), 512);
    tsplit_kernel<<<dim3(5,  64), dim3(32, 8)>>>(w1, bp(OFF_W1H), bp(OFF_W1L), 160);
    tsplit_kernel<<<dim3(2,  64), dim3(32, 8)>>>(tdw1, bp(OFF_TDH), bp(OFF_TDL), 64);

    // 3. mbuf = tanh(xxx @ w1)  [T,160]
    hm_gemm<1><<<dim3(2, 16), 256, HM_SMEM>>>(bp(OFF_XXH), bp(OFF_XXL),
        bp(OFF_W1H), bp(OFF_W1L), S + OFF_MBUF, 160, 160);

    // 4. xb branches (K=32) -> bf16 hi/lo
    gemm_branch<<<dim3(16, 16, 5), 256>>>(S + OFF_MBUF, w2, x, S + OFF_SX,
                                          S + OFF_MAA, bp(OFF_XBH), bp(OFF_XBL));

    // 5. r, k, v projections
    hm_gemm<0><<<dim3(16, 16), 256, HM_SMEM>>>(bp(OFF_XBH), bp(OFF_XBL),
        bp(OFF_WQH), bp(OFF_WQL), S + OFF_R, 2048, 2048);
    hm_gemm<0><<<dim3(4, 16), 256, HM_SMEM>>>(bp(OFF_XBH) + TC, bp(OFF_XBL) + TC,
        bp(OFF_WKH), bp(OFF_WKL), S + OFF_KR, 512, 512);
    hm_gemm<0><<<dim3(4, 16), 256, HM_SMEM>>>(bp(OFF_XBH) + 2 * TC, bp(OFF_XBL) + 2 * TC,
        bp(OFF_WVH), bp(OFF_WVL), S + OFF_V, 512, 512);

    // 6. d1 = tanh(xw @ tdw1) [T,64]; decay epilogue
    hm_gemm<1><<<dim3(1, 16), 256, HM_SMEM>>>(bp(OFF_XBH) + 3 * TC, bp(OFF_XBL) + 3 * TC,
        bp(OFF_TDH), bp(OFF_TDL), S + OFF_D1, 64, 64);
    gemm_decay<<<dim3(16, 16), 256>>>(S + OFF_D1, tdw2, tdec, S + OFF_KR,
                                      S + OFF_EW, S + OFF_KK);

    // 7. g = sigmoid(xg @ Wg)
    hm_gemm<2><<<dim3(16, 16), 256, HM_SMEM>>>(bp(OFF_XBH) + 4 * TC, bp(OFF_XBL) + 4 * TC,
        bp(OFF_WGH), bp(OFF_WGL), S + OFF_G, 2048, 2048);

    // 8. scan (fuses g-gate, emits og bf16 hi/lo)
    scan_kernel<<<dim3(4, 32), 256>>>(S + OFF_R, S + OFF_KK, S + OFF_EW, S + OFF_V,
                                      ns, state, S + OFF_G,
                                      bp(OFF_OGH), bp(OFF_OGL), S + OFF_SF);

    // 9. out = og @ Wo
    hm_gemm<0><<<dim3(16, 16), 256, HM_SMEM>>>(bp(OFF_OGH), bp(OFF_OGL),
        bp(OFF_WOH), bp(OFF_WOL), out, 2048, 2048);

    // 10. new_state
    if ((size_t)out_size >= TC + 65 * 2048) {
        tail_kernel<<<(65 * 2048 + 255) / 256, 256>>>(x, lenp, S + OFF_SF, out);
    }
}

// round 11
// speedup vs baseline: 1.9790x; 1.4928x over previous
#include <cuda_runtime.h>
#include <cuda_bf16.h>
#include <cstdint>
#include <cstddef>

constexpr int Tn = 2048;
constexpr size_t TC = (size_t)Tn * 2048;  // 4194304

// ---------------- scratch layout (float units) ----------------
constexpr size_t OFF_SX   = 0;                         // TC
constexpr size_t OFF_MAA  = OFF_SX   + TC;             // 5*2048
constexpr size_t OFF_MBUF = OFF_MAA  + 5 * 2048;       // T*160
constexpr size_t OFF_D1   = OFF_MBUF + (size_t)Tn*160; // T*64
constexpr size_t OFF_EW   = OFF_D1   + (size_t)Tn*64;  // TC
constexpr size_t OFF_KK   = OFF_EW   + TC;             // TC
constexpr size_t OFF_G    = OFF_KK   + TC;             // TC
constexpr size_t OFF_R    = OFF_G    + TC;             // TC
constexpr size_t OFF_KR   = OFF_R    + TC;             // T*512
constexpr size_t OFF_V    = OFF_KR   + (size_t)Tn*512; // T*512
constexpr size_t OFF_SF   = OFF_V    + (size_t)Tn*512; // 131072
constexpr size_t OFF_XXH = OFF_SF  + 131072;
constexpr size_t OFF_XXL = OFF_XXH + TC/2;
constexpr size_t OFF_XBH = OFF_XXL + TC/2;          // 5*TC bf16
constexpr size_t OFF_XBL = OFF_XBH + 5*TC/2;
constexpr size_t OFF_OGH = OFF_XBL + 5*TC/2;
constexpr size_t OFF_OGL = OFF_OGH + TC/2;
constexpr size_t OFF_WQH = OFF_OGL + TC/2;
constexpr size_t OFF_WQL = OFF_WQH + TC/2;
constexpr size_t OFF_WGH = OFF_WQL + TC/2;
constexpr size_t OFF_WGL = OFF_WGH + TC/2;
constexpr size_t OFF_WOH = OFF_WGL + TC/2;
constexpr size_t OFF_WOL = OFF_WOH + TC/2;
constexpr size_t OFF_WKH = OFF_WOL + TC/2;
constexpr size_t OFF_WKL = OFF_WKH + (size_t)512*1024;
constexpr size_t OFF_WVH = OFF_WKL + (size_t)512*1024;
constexpr size_t OFF_WVL = OFF_WVH + (size_t)512*1024;
constexpr size_t OFF_W1H = OFF_WVL + (size_t)512*1024;
constexpr size_t OFF_W1L = OFF_W1H + (size_t)160*1024;
constexpr size_t OFF_TDH = OFF_W1L + (size_t)160*1024;
constexpr size_t OFF_TDL = OFF_TDH + (size_t)64*1024;
constexpr size_t SCRATCH_TOTAL = OFF_TDL + (size_t)64*1024;

__device__ float g_scratch[SCRATCH_TOTAL];

// ---------------- PTX helpers (standard ISA only) ----------------
__device__ __forceinline__ uint32_t smem_u32(const void* p) {
    uint32_t a;
    asm("{ .reg .u64 t; cvta.to.shared.u64 t, %1; cvt.u32.u64 %0, t; }" : "=r"(a) : "l"(p));
    return a;
}
__device__ __forceinline__ void ldsm4(uint32_t& r0, uint32_t& r1, uint32_t& r2,
                                      uint32_t& r3, uint32_t a) {
    asm volatile("ldmatrix.sync.aligned.m8n8.x4.shared.b16 {%0,%1,%2,%3}, [%4];"
        : "=r"(r0), "=r"(r1), "=r"(r2), "=r"(r3) : "r"(a));
}
__device__ __forceinline__ void mma16816(float* c, const uint32_t* a, const uint32_t* b) {
    asm volatile("mma.sync.aligned.m16n8k16.row.col.f32.bf16.bf16.f32 "
        "{%0,%1,%2,%3}, {%4,%5,%6,%7}, {%8,%9}, {%0,%1,%2,%3};"
        : "+f"(c[0]), "+f"(c[1]), "+f"(c[2]), "+f"(c[3])
        : "r"(a[0]), "r"(a[1]), "r"(a[2]), "r"(a[3]), "r"(b[0]), "r"(b[1]));
}
#define CP_ASYNC(dst, src, sz) \
    asm volatile("cp.async.cg.shared.global [%0], [%1], 16, %2;" \
        :: "r"(dst), "l"(src), "r"(sz))
#define CP_COMMIT() asm volatile("cp.async.commit_group;" ::: "memory")
#define CP_WAIT(n)  asm volatile("cp.async.wait_group %0;" :: "n"(n) : "memory")
__device__ __forceinline__ uint32_t swz(uint32_t x) { return x ^ ((x >> 3) & 0x70); }

// ---------------- prep ----------------
__global__ void prep_kernel(const float* __restrict__ x, const float* __restrict__ state,
                            const unsigned char* __restrict__ ns,
                            const float* __restrict__ tmx,
                            const float* __restrict__ tmr, const float* __restrict__ tmk,
                            const float* __restrict__ tmv, const float* __restrict__ tmw,
                            const float* __restrict__ tmg,
                            float* __restrict__ sx,
                            __nv_bfloat16* __restrict__ xxh, __nv_bfloat16* __restrict__ xxl,
                            float* __restrict__ maacat) {
    size_t idx = (size_t)blockIdx.x * blockDim.x + threadIdx.x;
    if (idx < TC) {
        int t = (int)(idx >> 11), c = (int)(idx & 2047);
        float prev = (t == 0) ? state[c] : x[idx - 2048];
        if (ns[t]) prev = 0.0f;
        float xv = x[idx];
        float sxv = prev - xv;
        sx[idx] = sxv;
        float xxx = xv + sxv * tmx[c];
        __nv_bfloat16 h = __float2bfloat16(xxx);
        xxh[idx] = h;
        xxl[idx] = __float2bfloat16(xxx - __bfloat162float(h));
    }
    if (idx < 5 * 2048) {
        int n = (int)(idx >> 11), c = (int)(idx & 2047);
        const float* p = (n == 0) ? tmr : (n == 1) ? tmk : (n == 2) ? tmv
                       : (n == 3) ? tmw : tmg;
        maacat[idx] = p[c];
    }
}

// ---------------- transpose+split: fp32 [2048, N] -> bf16 hi/lo [N, 2048] ----
__global__ void tsplit_kernel(const float* __restrict__ src,
                              __nv_bfloat16* __restrict__ dh,
                              __nv_bfloat16* __restrict__ dl, int N) {
    __shared__ float smt[32][33];
    int n0 = blockIdx.x * 32, k0 = blockIdx.y * 32;
    int tx = threadIdx.x, ty = threadIdx.y;
#pragma unroll
    for (int r = 0; r < 4; r++)
        smt[ty + r * 8][tx] = src[(size_t)(k0 + ty + r * 8) * N + n0 + tx];
    __syncthreads();
#pragma unroll
    for (int r = 0; r < 4; r++) {
        float v = smt[tx][ty + r * 8];
        __nv_bfloat16 h = __float2bfloat16(v);
        size_t o = (size_t)(n0 + ty + r * 8) * 2048 + k0 + tx;
        dh[o] = h;
        dl[o] = __float2bfloat16(v - __bfloat162float(h));
    }
}

// ===========================================================================
// HMMA bf16 hi/lo GEMM. C[2048, N] = epi(A @ B^T), K=2048.
// CTA tile 128 x TN, BK=64, 2-stage cp.async pipeline, 512 threads.
// 16 warps = 4(M) x 4(N); warp tile 32 x (TN/4).
// 3-term compensation: AhBh + AhBl + AlBh. epi runtime: 0 plain,1 tanh,2 sigm.
// Dual task sets selected by blockIdx.z.
// ===========================================================================
template <int TN>
__global__ __launch_bounds__(512, 1)
void hm_gemm(const __nv_bfloat16* __restrict__ A0h, const __nv_bfloat16* __restrict__ A0l,
             const __nv_bfloat16* __restrict__ B0h, const __nv_bfloat16* __restrict__ B0l,
             float* __restrict__ C0, int N0, int ldc0, int epi0,
             const __nv_bfloat16* __restrict__ A1h, const __nv_bfloat16* __restrict__ A1l,
             const __nv_bfloat16* __restrict__ B1h, const __nv_bfloat16* __restrict__ B1l,
             float* __restrict__ C1, int N1, int ldc1, int epi1) {
    constexpr int ASZ = 128 * 128;      // bytes per A operand per stage
    constexpr int BSZ = TN * 128;
    constexpr int STG = 2 * ASZ + 2 * BSZ;
    constexpr int NG  = TN / 64;        // n16 groups per warp (4 or 2)

    const __nv_bfloat16 *Ah, *Al, *Bh, *Bl;
    float* C; int N, ldc, epi;
    if (blockIdx.z == 0) { Ah=A0h; Al=A0l; Bh=B0h; Bl=B0l; C=C0; N=N0; ldc=ldc0; epi=epi0; }
    else                 { Ah=A1h; Al=A1l; Bh=B1h; Bl=B1l; C=C1; N=N1; ldc=ldc1; epi=epi1; }

    extern __shared__ char sm[];
    uint32_t sb = smem_u32(sm);
    int tid = threadIdx.x, wid = tid >> 5, lane = tid & 31;
    int bx = blockIdx.x, by = blockIdx.y;
    int wm = wid >> 2, wn = wid & 3;

    auto load_stage = [&](int s, int kc) {
#pragma unroll
        for (int i = 0; i < 2; i++) {               // A: 128 rows x 8 chunks
            int chunk = tid + 512 * i;
            int row = chunk >> 3, c = chunk & 7;
            uint32_t dst = sb + s * STG + swz(row * 128 + c * 16);
            size_t go = (size_t)(by * 128 + row) * 2048 + kc + c * 8;
            CP_ASYNC(dst,       Ah + go, 16);
            CP_ASYNC(dst + ASZ, Al + go, 16);
        }
#pragma unroll
        for (int i = 0; i < NG; i++) {              // B: TN rows x 8 chunks
            int chunk = tid + 512 * i;
            int row = chunk >> 3, c = chunk & 7;
            int gn = bx * TN + row;
            int bsz = (gn < N) ? 16 : 0;
            uint32_t dst = sb + s * STG + 2 * ASZ + swz(row * 128 + c * 16);
            size_t go = (size_t)gn * 2048 + kc + c * 8;
            CP_ASYNC(dst,       Bh + go, bsz);
            CP_ASYNC(dst + BSZ, Bl + go, bsz);
        }
        CP_COMMIT();
    };

    load_stage(0, 0);
    load_stage(1, 64);

    float acc[2][2 * NG][4];
#pragma unroll
    for (int a = 0; a < 2; a++)
#pragma unroll
        for (int b = 0; b < 2 * NG; b++)
#pragma unroll
            for (int d = 0; d < 4; d++) acc[a][b][d] = 0.0f;

    const int arow = lane & 15;
    const int ahalf = lane >> 4;
    const int brow = (lane & 7) + ((lane >> 4) << 3);
    const int bhalf = (lane >> 3) & 1;

    for (int it = 0; it < 32; it++) {
        if (it == 31) { CP_WAIT(0); } else { CP_WAIT(1); }
        __syncthreads();

        uint32_t sA = sb + (it & 1) * STG;
        uint32_t sB = sA + 2 * ASZ;
#pragma unroll
        for (int ks = 0; ks < 4; ks++) {
            uint32_t bh[4][4], bl[4][4];
#pragma unroll
            for (int p = 0; p < NG; p++) {
                int rn = wn * (TN / 4) + p * 16 + brow;
                int c = ks * 2 + bhalf;
                uint32_t addr = sB + swz((uint32_t)(rn * 128 + c * 16));
                ldsm4(bh[p][0], bh[p][1], bh[p][2], bh[p][3], addr);
                ldsm4(bl[p][0], bl[p][1], bl[p][2], bl[p][3], addr + BSZ);
            }
#pragma unroll
            for (int mt = 0; mt < 2; mt++) {
                int rm = wm * 32 + mt * 16 + arow;
                int c = ks * 2 + ahalf;
                uint32_t addr = sA + swz((uint32_t)(rm * 128 + c * 16));
                uint32_t ah[4], al[4];
                ldsm4(ah[0], ah[1], ah[2], ah[3], addr);
                ldsm4(al[0], al[1], al[2], al[3], addr + ASZ);
#pragma unroll
                for (int oc = 0; oc < 2 * NG; oc++) {
                    uint32_t bsh[2] = { bh[oc >> 1][(oc & 1) * 2], bh[oc >> 1][(oc & 1) * 2 + 1] };
                    uint32_t bsl[2] = { bl[oc >> 1][(oc & 1) * 2], bl[oc >> 1][(oc & 1) * 2 + 1] };
                    mma16816(acc[mt][oc], ah, bsh);
                    mma16816(acc[mt][oc], ah, bsl);
                    mma16816(acc[mt][oc], al, bsh);
                }
            }
        }
        __syncthreads();
        if (it + 2 < 32) load_stage(it & 1, (it + 2) * 64);
    }

    // epilogue
    int r0 = by * 128 + wm * 32;
    int c0 = bx * TN + wn * (TN / 4);
#pragma unroll
    for (int mt = 0; mt < 2; mt++) {
#pragma unroll
        for (int oc = 0; oc < 2 * NG; oc++) {
            int col = c0 + oc * 8 + (lane & 3) * 2;
            if (col >= N) continue;
            int row = r0 + mt * 16 + (lane >> 2);
            float v0 = acc[mt][oc][0], v1 = acc[mt][oc][1];
            float v2 = acc[mt][oc][2], v3 = acc[mt][oc][3];
            if (epi == 1) { v0 = tanhf(v0); v1 = tanhf(v1); v2 = tanhf(v2); v3 = tanhf(v3); }
            else if (epi == 2) {
                v0 = 1.f/(1.f+expf(-v0)); v1 = 1.f/(1.f+expf(-v1));
                v2 = 1.f/(1.f+expf(-v2)); v3 = 1.f/(1.f+expf(-v3));
            }
            *(float2*)(C + (size_t)row * ldc + col) = make_float2(v0, v1);
            *(float2*)(C + (size_t)(row + 8) * ldc + col) = make_float2(v2, v3);
        }
    }
}

// ---------------- SIMT K=32: xb[z] = x + sx*(maa_z + mbuf_z @ w2_z) -> bf16
__global__ __launch_bounds__(256)
void gemm_branch(const float* __restrict__ A, const float* __restrict__ B,
                 const float* __restrict__ x, const float* __restrict__ sx,
                 const float* __restrict__ maa,
                 __nv_bfloat16* __restrict__ xbh, __nv_bfloat16* __restrict__ xbl) {
    int z = blockIdx.z;
    A += z * 32;
    B += (size_t)z * 32 * 2048;
    maa += (size_t)z * 2048;
    __nv_bfloat16* oh = xbh + (size_t)z * TC;
    __nv_bfloat16* ol = xbl + (size_t)z * TC;

    __shared__ float As[8][128], Bs[8][128];
    int tid = threadIdx.x, tx = tid & 15, ty = tid >> 4;
    int bx = blockIdx.x, by = blockIdx.y;
    float acc[8][8];
#pragma unroll
    for (int i = 0; i < 8; i++)
#pragma unroll
        for (int j = 0; j < 8; j++) acc[i][j] = 0.0f;
    int ar = tid >> 1, ac = (tid & 1) * 4, br = tid >> 5, bc = (tid & 31) * 4;
    for (int k0 = 0; k0 < 32; k0 += 8) {
        float4 av = *(const float4*)(A + (size_t)(by * 128 + ar) * 160 + k0 + ac);
        As[ac+0][ar] = av.x; As[ac+1][ar] = av.y; As[ac+2][ar] = av.z; As[ac+3][ar] = av.w;
        *(float4*)&Bs[br][bc] = *(const float4*)(B + (size_t)(k0 + br) * 2048 + bx * 128 + bc);
        __syncthreads();
#pragma unroll
        for (int kk = 0; kk < 8; kk++) {
            float a[8], b[8];
#pragma unroll
            for (int i = 0; i < 8; i++) a[i] = As[kk][ty * 8 + i];
#pragma unroll
            for (int j = 0; j < 8; j++) b[j] = Bs[kk][tx * 8 + j];
#pragma unroll
            for (int i = 0; i < 8; i++)
#pragma unroll
                for (int j = 0; j < 8; j++) acc[i][j] += a[i] * b[j];
        }
        __syncthreads();
    }
    int row0 = by * 128 + ty * 8, col0 = bx * 128 + tx * 8;
#pragma unroll
    for (int i = 0; i < 8; i++)
#pragma unroll
        for (int j = 0; j < 8; j++) {
            int col = col0 + j;
            size_t idx = (size_t)(row0 + i) * 2048 + col;
            float val = x[idx] + sx[idx] * (maa[col] + acc[i][j]);
            __nv_bfloat16 h = __float2bfloat16(val);
            oh[idx] = h;
            ol[idx] = __float2bfloat16(val - __bfloat162float(h));
        }
}

// ---------------- SIMT K=64: decay -> ew, kk ----------------
__global__ __launch_bounds__(256)
void gemm_decay(const float* __restrict__ A, const float* __restrict__ B,
                const float* __restrict__ bias, const float* __restrict__ kin,
                float* __restrict__ ewo, float* __restrict__ kko) {
    __shared__ float As[8][128], Bs[8][128];
    int tid = threadIdx.x, tx = tid & 15, ty = tid >> 4;
    int bx = blockIdx.x, by = blockIdx.y;
    float acc[8][8];
#pragma unroll
    for (int i = 0; i < 8; i++)
#pragma unroll
        for (int j = 0; j < 8; j++) acc[i][j] = 0.0f;
    int ar = tid >> 1, ac = (tid & 1) * 4, br = tid >> 5, bc = (tid & 31) * 4;
    for (int k0 = 0; k0 < 64; k0 += 8) {
        float4 av = *(const float4*)(A + (size_t)(by * 128 + ar) * 64 + k0 + ac);
        As[ac+0][ar] = av.x; As[ac+1][ar] = av.y; As[ac+2][ar] = av.z; As[ac+3][ar] = av.w;
        *(float4*)&Bs[br][bc] = *(const float4*)(B + (size_t)(k0 + br) * 2048 + bx * 128 + bc);
        __syncthreads();
#pragma unroll
        for (int kk = 0; kk < 8; kk++) {
            float a[8], b[8];
#pragma unroll
            for (int i = 0; i < 8; i++) a[i] = As[kk][ty * 8 + i];
#pragma unroll
            for (int j = 0; j < 8; j++) b[j] = Bs[kk][tx * 8 + j];
#pragma unroll
            for (int i = 0; i < 8; i++)
#pragma unroll
                for (int j = 0; j < 8; j++) acc[i][j] += a[i] * b[j];
        }
        __syncthreads();
    }
    int row0 = by * 128 + ty * 8, col0 = bx * 128 + tx * 8;
#pragma unroll
    for (int i = 0; i < 8; i++) {
        int row = row0 + i;
#pragma unroll
        for (int j = 0; j < 8; j++) {
            int col = col0 + j;
            float dec = acc[i][j] + bias[col];
            float lw = fmaxf(-expf(dec), -5.0f);
            float ew = expf(lw);
            size_t oidx = (size_t)row * 2048 + col;
            ewo[oidx] = ew;
            float kvv = kin[(size_t)row * 512 + (col >> 8) * 64 + (col & 63)];
            kko[oidx] = kvv * (1.0f - ew);
        }
    }
}

// ---------------- scan: prefetch + deferred reduce; og = (o*g) bf16 hi/lo --
__global__ __launch_bounds__(256)
void scan_kernel(const float* __restrict__ r, const float* __restrict__ kk,
                 const float* __restrict__ ew, const float* __restrict__ v,
                 const unsigned char* __restrict__ ns,
                 const float* __restrict__ state, const float* __restrict__ g,
                 __nv_bfloat16* __restrict__ ogh, __nv_bfloat16* __restrict__ ogl,
                 float* __restrict__ sfin) {
    int h = blockIdx.y, vs = blockIdx.x * 16;
    int tid = threadIdx.x, vl = tid >> 4, kg = tid & 15;
    int vcol = vs + vl, hv4 = (h >> 2) * 64;

    float s[4];
#pragma unroll
    for (int i = 0; i < 4; i++)
        s[i] = state[2048 + h * 4096 + (kg * 4 + i) * 64 + vcol];

    __shared__ float rs[2][64], ks[2][64], ws[2][64], vsd[2][16];
    __shared__ float pob[2][16][16];

    float reg = 0.0f;
    {
        size_t base = (size_t)h * 64;
        if (tid < 64)       reg = r[base + tid];
        else if (tid < 128) reg = kk[base + tid - 64];
        else if (tid < 192) reg = ew[base + tid - 128];
        else if (tid < 208) reg = v[hv4 + vs + tid - 192];
    }
    unsigned char nsr = ns[0];

    for (int t = 0; t < Tn; t++) {
        int b = t & 1;
        if (tid < 64)       rs[b][tid] = reg;
        else if (tid < 128) ks[b][tid - 64] = reg;
        else if (tid < 192) ws[b][tid - 128] = reg;
        else if (tid < 208) vsd[b][tid - 192] = reg;
        __syncthreads();

        unsigned char nsn = 0;
        if (t + 1 < Tn) {
            size_t base = (size_t)(t + 1) * 2048 + h * 64;
            if (tid < 64)       reg = r[base + tid];
            else if (tid < 128) reg = kk[base + tid - 64];
            else if (tid < 192) reg = ew[base + tid - 128];
            else if (tid < 208) reg = v[(size_t)(t + 1) * 512 + hv4 + vs + tid - 192];
            nsn = ns[t + 1];
        }

        if (t > 0 && kg == 0) {
            float acc = 0.0f;
#pragma unroll
            for (int i = 0; i < 16; i++) acc += pob[1 - b][i][vl];
            size_t ob = (size_t)(t - 1) * 2048 + h * 64 + vcol;
            float val = acc * g[ob];
            __nv_bfloat16 hh = __float2bfloat16(val);
            ogh[ob] = hh;
            ogl[ob] = __float2bfloat16(val - __bfloat162float(hh));
        }

        if (nsr) { s[0] = 0.f; s[1] = 0.f; s[2] = 0.f; s[3] = 0.f; }
        float vv = vsd[b][vl];
        float po = 0.0f;
#pragma unroll
        for (int i = 0; i < 4; i++) {
            int krow = kg * 4 + i;
            s[i] = s[i] * ws[b][krow] + ks[b][krow] * vv;
            po += rs[b][krow] * s[i];
        }
        pob[b][kg][vl] = po;
        nsr = nsn;
    }
    __syncthreads();
    if (kg == 0) {
        float acc = 0.0f;
#pragma unroll
        for (int i = 0; i < 16; i++) acc += pob[1][i][vl];
        size_t ob = (size_t)(Tn - 1) * 2048 + h * 64 + vcol;
        float val = acc * g[ob];
        __nv_bfloat16 hh = __float2bfloat16(val);
        ogh[ob] = hh;
        ogl[ob] = __float2bfloat16(val - __bfloat162float(hh));
    }
#pragma unroll
    for (int i = 0; i < 4; i++)
        sfin[h * 4096 + (kg * 4 + i) * 64 + vcol] = s[i];
}

// ---------------- tail ----------------
__global__ void tail_kernel(const float* __restrict__ x, const int* __restrict__ lenp,
                            const float* __restrict__ sfin, float* __restrict__ out) {
    int idx = blockIdx.x * blockDim.x + threadIdx.x;
    if (idx >= 65 * 2048) return;
    int len = *lenp;
    out[TC + idx] = (idx < 2048) ? x[(size_t)(len - 1) * 2048 + idx] : sfin[idx - 2048];
}

// ---------------------------------------------------------------------------
extern "C" void kernel_launch(void* const* d_in, const int* in_sizes, int n_in,
                              void* d_out, int out_size) {
    (void)in_sizes; (void)n_in;
    const float* x     = (const float*)d_in[0];
    const float* state = (const float*)d_in[1];
    const unsigned char* ns = (const unsigned char*)d_in[2];
    const int* lenp    = (const int*)d_in[3];
    const float* tmx   = (const float*)d_in[4];
    const float* tmr   = (const float*)d_in[5];
    const float* tmk   = (const float*)d_in[6];
    const float* tmv   = (const float*)d_in[7];
    const float* tmw   = (const float*)d_in[8];
    const float* tmg   = (const float*)d_in[9];
    const float* w1    = (const float*)d_in[10];
    const float* w2    = (const float*)d_in[11];
    const float* tdec  = (const float*)d_in[12];
    const float* tdw1  = (const float*)d_in[13];
    const float* tdw2  = (const float*)d_in[14];
    const float* Wq    = (const float*)d_in[15];
    const float* Wk    = (const float*)d_in[16];
    const float* Wv    = (const float*)d_in[17];
    const float* Wg    = (const float*)d_in[18];
    const float* Wo    = (const float*)d_in[19];
    float* out = (float*)d_out;

    float* S = nullptr;
    cudaGetSymbolAddress((void**)&S, g_scratch);
    auto bp = [&](size_t off) { return (__nv_bfloat16*)(S + off); };

    constexpr int SM256 = (2 * 128 * 128 + 2 * 256 * 128) * 2;  // 196608
    constexpr int SM128 = (2 * 128 * 128 + 2 * 128 * 128) * 2;  // 131072
    cudaFuncSetAttribute(hm_gemm<256>, cudaFuncAttributeMaxDynamicSharedMemorySize, SM256);
    cudaFuncSetAttribute(hm_gemm<128>, cudaFuncAttributeMaxDynamicSharedMemorySize, SM128);

    // 1. prep
    prep_kernel<<<(unsigned)((TC + 255) / 256), 256>>>(
        x, state, ns, tmx, tmr, tmk, tmv, tmw, tmg,
        S + OFF_SX, bp(OFF_XXH), bp(OFF_XXL), S + OFF_MAA);

    // 2. weight transpose + split
    tsplit_kernel<<<dim3(64, 64), dim3(32, 8)>>>(Wq, bp(OFF_WQH), bp(OFF_WQL), 2048);
    tsplit_kernel<<<dim3(64, 64), dim3(32, 8)>>>(Wg, bp(OFF_WGH), bp(OFF_WGL), 2048);
    tsplit_kernel<<<dim3(64, 64), dim3(32, 8)>>>(Wo, bp(OFF_WOH), bp(OFF_WOL), 2048);
    tsplit_kernel<<<dim3(16, 64), dim3(32, 8)>>>(Wk, bp(OFF_WKH), bp(OFF_WKL), 512);
    tsplit_kernel<<<dim3(16, 64), dim3(32, 8)>>>(Wv, bp(OFF_WVH), bp(OFF_WVL), 512);
    tsplit_kernel<<<dim3(5,  64), dim3(32, 8)>>>(w1, bp(OFF_W1H), bp(OFF_W1L), 160);
    tsplit_kernel<<<dim3(2,  64), dim3(32, 8)>>>(tdw1, bp(OFF_TDH), bp(OFF_TDL), 64);

    // 3. mbuf = tanh(xxx @ w1)  [T,160]
    hm_gemm<128><<<dim3(2, 16, 1), 512, SM128>>>(
        bp(OFF_XXH), bp(OFF_XXL), bp(OFF_W1H), bp(OFF_W1L), S + OFF_MBUF, 160, 160, 1,
        bp(OFF_XXH), bp(OFF_XXL), bp(OFF_W1H), bp(OFF_W1L), S + OFF_MBUF, 160, 160, 1);

    // 4. xb branches (K=32) -> bf16 hi/lo
    gemm_branch<<<dim3(16, 16, 5), 256>>>(S + OFF_MBUF, w2, x, S + OFF_SX,
                                          S + OFF_MAA, bp(OFF_XBH), bp(OFF_XBL));

    // 5. r = xr@Wq (plain) and g = sigmoid(xg@Wg), one dual launch
    hm_gemm<256><<<dim3(8, 16, 2), 512, SM256>>>(
        bp(OFF_XBH), bp(OFF_XBL), bp(OFF_WQH), bp(OFF_WQL), S + OFF_R, 2048, 2048, 0,
        bp(OFF_XBH) + 4 * TC, bp(OFF_XBL) + 4 * TC, bp(OFF_WGH), bp(OFF_WGL), S + OFF_G, 2048, 2048, 2);

    // 6. k and v, one dual launch
    hm_gemm<128><<<dim3(4, 16, 2), 512, SM128>>>(
        bp(OFF_XBH) + TC, bp(OFF_XBL) + TC, bp(OFF_WKH), bp(OFF_WKL), S + OFF_KR, 512, 512, 0,
        bp(OFF_XBH) + 2 * TC, bp(OFF_XBL) + 2 * TC, bp(OFF_WVH), bp(OFF_WVL), S + OFF_V, 512, 512, 0);

    // 7. d1 = tanh(xw @ tdw1) [T,64]; decay epilogue
    hm_gemm<128><<<dim3(1, 16, 1), 512, SM128>>>(
        bp(OFF_XBH) + 3 * TC, bp(OFF_XBL) + 3 * TC, bp(OFF_TDH), bp(OFF_TDL), S + OFF_D1, 64, 64, 1,
        bp(OFF_XBH) + 3 * TC, bp(OFF_XBL) + 3 * TC, bp(OFF_TDH), bp(OFF_TDL), S + OFF_D1, 64, 64, 1);
    gemm_decay<<<dim3(16, 16), 256>>>(S + OFF_D1, tdw2, tdec, S + OFF_KR,
                                      S + OFF_EW, S + OFF_KK);

    // 8. scan (fuses g-gate, emits og bf16 hi/lo)
    scan_kernel<<<dim3(4, 32), 256>>>(S + OFF_R, S + OFF_KK, S + OFF_EW, S + OFF_V,
                                      ns, state, S + OFF_G,
                                      bp(OFF_OGH), bp(OFF_OGL), S + OFF_SF);

    // 9. out = og @ Wo
    hm_gemm<256><<<dim3(8, 16, 1), 512, SM256>>>(
        bp(OFF_OGH), bp(OFF_OGL), bp(OFF_WOH), bp(OFF_WOL), out, 2048, 2048, 0,
        bp(OFF_OGH), bp(OFF_OGL), bp(OFF_WOH), bp(OFF_WOL), out, 2048, 2048, 0);

    // 10. new_state
    if ((size_t)out_size >= TC + 65 * 2048) {
        tail_kernel<<<(65 * 2048 + 255) / 256, 256>>>(x, lenp, S + OFF_SF, out);
    }
}

// round 13
// speedup vs baseline: 1.9988x; 1.0100x over previous
#include <cuda_runtime.h>
#include <cuda_bf16.h>
#include <cstdint>
#include <cstddef>

constexpr int Tn = 2048;
constexpr size_t TC = (size_t)Tn * 2048;  // 4194304

// ---------------- scratch layout (float units) ----------------
constexpr size_t OFF_SX   = 0;                         // TC
constexpr size_t OFF_MAA  = OFF_SX   + TC;             // 5*2048
constexpr size_t OFF_MBUF = OFF_MAA  + 5 * 2048;       // T*160
constexpr size_t OFF_D1   = OFF_MBUF + (size_t)Tn*160; // T*64
constexpr size_t OFF_EW   = OFF_D1   + (size_t)Tn*64;  // TC
constexpr size_t OFF_KK   = OFF_EW   + TC;             // TC
constexpr size_t OFF_G    = OFF_KK   + TC;             // TC
constexpr size_t OFF_R    = OFF_G    + TC;             // TC
constexpr size_t OFF_KR   = OFF_R    + TC;             // T*512
constexpr size_t OFF_V    = OFF_KR   + (size_t)Tn*512; // T*512
constexpr size_t OFF_SF   = OFF_V    + (size_t)Tn*512; // 131072
constexpr size_t OFF_XXH = OFF_SF  + 131072;
constexpr size_t OFF_XXL = OFF_XXH + TC/2;
constexpr size_t OFF_XBH = OFF_XXL + TC/2;          // 5*TC bf16
constexpr size_t OFF_XBL = OFF_XBH + 5*TC/2;
constexpr size_t OFF_OGH = OFF_XBL + 5*TC/2;
constexpr size_t OFF_OGL = OFF_OGH + TC/2;
constexpr size_t OFF_WQH = OFF_OGL + TC/2;
constexpr size_t OFF_WQL = OFF_WQH + TC/2;
constexpr size_t OFF_WGH = OFF_WQL + TC/2;
constexpr size_t OFF_WGL = OFF_WGH + TC/2;
constexpr size_t OFF_WOH = OFF_WGL + TC/2;
constexpr size_t OFF_WOL = OFF_WOH + TC/2;
constexpr size_t OFF_WKH = OFF_WOL + TC/2;
constexpr size_t OFF_WKL = OFF_WKH + (size_t)512*1024;
constexpr size_t OFF_WVH = OFF_WKL + (size_t)512*1024;
constexpr size_t OFF_WVL = OFF_WVH + (size_t)512*1024;
constexpr size_t OFF_W1H = OFF_WVL + (size_t)512*1024;
constexpr size_t OFF_W1L = OFF_W1H + (size_t)160*1024;
constexpr size_t OFF_TDH = OFF_W1L + (size_t)160*1024;
constexpr size_t OFF_TDL = OFF_TDH + (size_t)64*1024;
constexpr size_t SCRATCH_TOTAL = OFF_TDL + (size_t)64*1024;

__device__ float g_scratch[SCRATCH_TOTAL];

// ---------------- PTX helpers (standard ISA only) ----------------
__device__ __forceinline__ uint32_t smem_u32(const void* p) {
    uint32_t a;
    asm("{ .reg .u64 t; cvta.to.shared.u64 t, %1; cvt.u32.u64 %0, t; }" : "=r"(a) : "l"(p));
    return a;
}
__device__ __forceinline__ void ldsm4(uint32_t& r0, uint32_t& r1, uint32_t& r2,
                                      uint32_t& r3, uint32_t a) {
    asm volatile("ldmatrix.sync.aligned.m8n8.x4.shared.b16 {%0,%1,%2,%3}, [%4];"
        : "=r"(r0), "=r"(r1), "=r"(r2), "=r"(r3) : "r"(a));
}
__device__ __forceinline__ void mma16816(float* c, const uint32_t* a, const uint32_t* b) {
    asm volatile("mma.sync.aligned.m16n8k16.row.col.f32.bf16.bf16.f32 "
        "{%0,%1,%2,%3}, {%4,%5,%6,%7}, {%8,%9}, {%0,%1,%2,%3};"
        : "+f"(c[0]), "+f"(c[1]), "+f"(c[2]), "+f"(c[3])
        : "r"(a[0]), "r"(a[1]), "r"(a[2]), "r"(a[3]), "r"(b[0]), "r"(b[1]));
}
#define CP_ASYNC(dst, src, sz) \
    asm volatile("cp.async.cg.shared.global [%0], [%1], 16, %2;" \
        :: "r"(dst), "l"(src), "r"(sz))
#define CP_COMMIT() asm volatile("cp.async.commit_group;" ::: "memory")
#define CP_WAIT(n)  asm volatile("cp.async.wait_group %0;" :: "n"(n) : "memory")
__device__ __forceinline__ uint32_t swz64(uint32_t x) { return x ^ ((x >> 3) & 0x30); }

// ---------------- prep ----------------
__global__ void prep_kernel(const float* __restrict__ x, const float* __restrict__ state,
                            const unsigned char* __restrict__ ns,
                            const float* __restrict__ tmx,
                            const float* __restrict__ tmr, const float* __restrict__ tmk,
                            const float* __restrict__ tmv, const float* __restrict__ tmw,
                            const float* __restrict__ tmg,
                            float* __restrict__ sx,
                            __nv_bfloat16* __restrict__ xxh, __nv_bfloat16* __restrict__ xxl,
                            float* __restrict__ maacat) {
    size_t idx = (size_t)blockIdx.x * blockDim.x + threadIdx.x;
    if (idx < TC) {
        int t = (int)(idx >> 11), c = (int)(idx & 2047);
        float prev = (t == 0) ? state[c] : x[idx - 2048];
        if (ns[t]) prev = 0.0f;
        float xv = x[idx];
        float sxv = prev - xv;
        sx[idx] = sxv;
        float xxx = xv + sxv * tmx[c];
        __nv_bfloat16 h = __float2bfloat16(xxx);
        xxh[idx] = h;
        xxl[idx] = __float2bfloat16(xxx - __bfloat162float(h));
    }
    if (idx < 5 * 2048) {
        int n = (int)(idx >> 11), c = (int)(idx & 2047);
        const float* p = (n == 0) ? tmr : (n == 1) ? tmk : (n == 2) ? tmv
                       : (n == 3) ? tmw : tmg;
        maacat[idx] = p[c];
    }
}

// ---------------- transpose+split: fp32 [2048, N] -> bf16 hi/lo [N, 2048] ----
__global__ void tsplit_kernel(const float* __restrict__ src,
                              __nv_bfloat16* __restrict__ dh,
                              __nv_bfloat16* __restrict__ dl, int N) {
    __shared__ float smt[32][33];
    int n0 = blockIdx.x * 32, k0 = blockIdx.y * 32;
    int tx = threadIdx.x, ty = threadIdx.y;
#pragma unroll
    for (int r = 0; r < 4; r++)
        smt[ty + r * 8][tx] = src[(size_t)(k0 + ty + r * 8) * N + n0 + tx];
    __syncthreads();
#pragma unroll
    for (int r = 0; r < 4; r++) {
        float v = smt[tx][ty + r * 8];
        __nv_bfloat16 h = __float2bfloat16(v);
        size_t o = (size_t)(n0 + ty + r * 8) * 2048 + k0 + tx;
        dh[o] = h;
        dl[o] = __float2bfloat16(v - __bfloat162float(h));
    }
}

// ===========================================================================
// HMMA bf16 hi/lo GEMM. C[2048, N] = epi(A @ B^T), K=2048.
// CTA tile 128x128, BK=32, 3-stage cp.async pipeline, 256 threads,
// ONE __syncthreads per iteration, 96KB SMEM -> 2 CTAs/SM.
// 8 warps = 2(M) x 4(N); warp tile 64x32.
// 3-term compensation: AhBh + AhBl + AlBh. epi: 0 plain, 1 tanh, 2 sigmoid.
// Dual task sets selected by blockIdx.z.
// ===========================================================================
constexpr int HG_ASZ = 128 * 32 * 2;            // 8192 B per A operand/stage
constexpr int HG_BSZ = 128 * 32 * 2;            // 8192 B per B operand/stage
constexpr int HG_STG = 2 * HG_ASZ + 2 * HG_BSZ; // 32768
constexpr int HG_SMEM = 3 * HG_STG;             // 98304

__global__ __launch_bounds__(256, 2)
void hm_gemm(const __nv_bfloat16* __restrict__ A0h, const __nv_bfloat16* __restrict__ A0l,
             const __nv_bfloat16* __restrict__ B0h, const __nv_bfloat16* __restrict__ B0l,
             float* __restrict__ C0, int N0, int ldc0, int epi0,
             const __nv_bfloat16* __restrict__ A1h, const __nv_bfloat16* __restrict__ A1l,
             const __nv_bfloat16* __restrict__ B1h, const __nv_bfloat16* __restrict__ B1l,
             float* __restrict__ C1, int N1, int ldc1, int epi1) {
    const __nv_bfloat16 *Ah, *Al, *Bh, *Bl;
    float* C; int N, ldc, epi;
    if (blockIdx.z == 0) { Ah=A0h; Al=A0l; Bh=B0h; Bl=B0l; C=C0; N=N0; ldc=ldc0; epi=epi0; }
    else                 { Ah=A1h; Al=A1l; Bh=B1h; Bl=B1l; C=C1; N=N1; ldc=ldc1; epi=epi1; }

    extern __shared__ char sm[];
    uint32_t sb = smem_u32(sm);
    int tid = threadIdx.x, wid = tid >> 5, lane = tid & 31;
    int bx = blockIdx.x, by = blockIdx.y;
    int wm = wid >> 2, wn = wid & 3;   // 2(M) x 4(N)

    auto load_stage = [&](int s, int kc) {
#pragma unroll
        for (int i = 0; i < 2; i++) {
            int chunk = tid + 256 * i;          // 0..511 -> 128 rows x 4 chunks
            int row = chunk >> 2, c = chunk & 3;
            uint32_t dst = sb + s * HG_STG + swz64(row * 64 + c * 16);
            size_t goa = (size_t)(by * 128 + row) * 2048 + kc + c * 8;
            CP_ASYNC(dst,          Ah + goa, 16);
            CP_ASYNC(dst + HG_ASZ, Al + goa, 16);
            int gn = bx * 128 + row;
            int bsz = (gn < N) ? 16 : 0;
            size_t gob = (size_t)gn * 2048 + kc + c * 8;
            CP_ASYNC(dst + 2 * HG_ASZ,          Bh + gob, bsz);
            CP_ASYNC(dst + 2 * HG_ASZ + HG_BSZ, Bl + gob, bsz);
        }
        CP_COMMIT();
    };

    load_stage(0, 0);
    load_stage(1, 32);

    float acc[4][4][4];
#pragma unroll
    for (int a = 0; a < 4; a++)
#pragma unroll
        for (int b = 0; b < 4; b++)
#pragma unroll
            for (int d = 0; d < 4; d++) acc[a][b][d] = 0.0f;

    const int arow = lane & 15;
    const int ahalf = lane >> 4;
    const int brow = (lane & 7) + ((lane >> 4) << 3);
    const int bhalf = (lane >> 3) & 1;

    int stage = 0;
    for (int it = 0; it < 64; it++) {
        if (it < 63) { CP_WAIT(1); } else { CP_WAIT(0); }
        __syncthreads();    // all warps done reading stage (it-1): slot (it+2)%3 free
        if (it + 2 < 64) {
            int s2 = stage + 2; if (s2 >= 3) s2 -= 3;
            load_stage(s2, (it + 2) * 32);
        }

        uint32_t sA = sb + stage * HG_STG;
        uint32_t sB = sA + 2 * HG_ASZ;
#pragma unroll
        for (int ks = 0; ks < 2; ks++) {
            int c = ks * 2;
            // B: warp's 32 columns = 2 groups of 16
            uint32_t bh[2][4], bl[2][4];
#pragma unroll
            for (int p = 0; p < 2; p++) {
                int rn = wn * 32 + p * 16 + brow;
                uint32_t addr = sB + swz64((uint32_t)(rn * 64 + (c + bhalf) * 16));
                ldsm4(bh[p][0], bh[p][1], bh[p][2], bh[p][3], addr);
                ldsm4(bl[p][0], bl[p][1], bl[p][2], bl[p][3], addr + HG_BSZ);
            }
#pragma unroll
            for (int mt = 0; mt < 4; mt++) {
                int rm = wm * 64 + mt * 16 + arow;
                uint32_t addr = sA + swz64((uint32_t)(rm * 64 + (c + ahalf) * 16));
                uint32_t ah[4], al[4];
                ldsm4(ah[0], ah[1], ah[2], ah[3], addr);
                ldsm4(al[0], al[1], al[2], al[3], addr + HG_ASZ);
#pragma unroll
                for (int oc = 0; oc < 4; oc++) {
                    uint32_t bsh[2] = { bh[oc >> 1][(oc & 1) * 2], bh[oc >> 1][(oc & 1) * 2 + 1] };
                    uint32_t bsl[2] = { bl[oc >> 1][(oc & 1) * 2], bl[oc >> 1][(oc & 1) * 2 + 1] };
                    mma16816(acc[mt][oc], ah, bsh);
                    mma16816(acc[mt][oc], ah, bsl);
                    mma16816(acc[mt][oc], al, bsh);
                }
            }
        }
        stage++; if (stage >= 3) stage = 0;
    }

    // epilogue
    int r0 = by * 128 + wm * 64;
    int c0 = bx * 128 + wn * 32;
#pragma unroll
    for (int mt = 0; mt < 4; mt++) {
#pragma unroll
        for (int oc = 0; oc < 4; oc++) {
            int col = c0 + oc * 8 + (lane & 3) * 2;
            if (col >= N) continue;
            int row = r0 + mt * 16 + (lane >> 2);
            float v0 = acc[mt][oc][0], v1 = acc[mt][oc][1];
            float v2 = acc[mt][oc][2], v3 = acc[mt][oc][3];
            if (epi == 1) { v0 = tanhf(v0); v1 = tanhf(v1); v2 = tanhf(v2); v3 = tanhf(v3); }
            else if (epi == 2) {
                v0 = 1.f/(1.f+expf(-v0)); v1 = 1.f/(1.f+expf(-v1));
                v2 = 1.f/(1.f+expf(-v2)); v3 = 1.f/(1.f+expf(-v3));
            }
            *(float2*)(C + (size_t)row * ldc + col) = make_float2(v0, v1);
            *(float2*)(C + (size_t)(row + 8) * ldc + col) = make_float2(v2, v3);
        }
    }
}

// ---------------- SIMT K=32: xb[z] = x + sx*(maa_z + mbuf_z @ w2_z) -> bf16
__global__ __launch_bounds__(256)
void gemm_branch(const float* __restrict__ A, const float* __restrict__ B,
                 const float* __restrict__ x, const float* __restrict__ sx,
                 const float* __restrict__ maa,
                 __nv_bfloat16* __restrict__ xbh, __nv_bfloat16* __restrict__ xbl) {
    int z = blockIdx.z;
    A += z * 32;
    B += (size_t)z * 32 * 2048;
    maa += (size_t)z * 2048;
    __nv_bfloat16* oh = xbh + (size_t)z * TC;
    __nv_bfloat16* ol = xbl + (size_t)z * TC;

    __shared__ float As[8][128], Bs[8][128];
    int tid = threadIdx.x, tx = tid & 15, ty = tid >> 4;
    int bx = blockIdx.x, by = blockIdx.y;
    float acc[8][8];
#pragma unroll
    for (int i = 0; i < 8; i++)
#pragma unroll
        for (int j = 0; j < 8; j++) acc[i][j] = 0.0f;
    int ar = tid >> 1, ac = (tid & 1) * 4, br = tid >> 5, bc = (tid & 31) * 4;
    for (int k0 = 0; k0 < 32; k0 += 8) {
        float4 av = *(const float4*)(A + (size_t)(by * 128 + ar) * 160 + k0 + ac);
        As[ac+0][ar] = av.x; As[ac+1][ar] = av.y; As[ac+2][ar] = av.z; As[ac+3][ar] = av.w;
        *(float4*)&Bs[br][bc] = *(const float4*)(B + (size_t)(k0 + br) * 2048 + bx * 128 + bc);
        __syncthreads();
#pragma unroll
        for (int kk = 0; kk < 8; kk++) {
            float a[8], b[8];
#pragma unroll
            for (int i = 0; i < 8; i++) a[i] = As[kk][ty * 8 + i];
#pragma unroll
            for (int j = 0; j < 8; j++) b[j] = Bs[kk][tx * 8 + j];
#pragma unroll
            for (int i = 0; i < 8; i++)
#pragma unroll
                for (int j = 0; j < 8; j++) acc[i][j] += a[i] * b[j];
        }
        __syncthreads();
    }
    int row0 = by * 128 + ty * 8, col0 = bx * 128 + tx * 8;
#pragma unroll
    for (int i = 0; i < 8; i++)
#pragma unroll
        for (int j = 0; j < 8; j++) {
            int col = col0 + j;
            size_t idx = (size_t)(row0 + i) * 2048 + col;
            float val = x[idx] + sx[idx] * (maa[col] + acc[i][j]);
            __nv_bfloat16 h = __float2bfloat16(val);
            oh[idx] = h;
            ol[idx] = __float2bfloat16(val - __bfloat162float(h));
        }
}

// ---------------- SIMT K=64: decay -> ew, kk ----------------
__global__ __launch_bounds__(256)
void gemm_decay(const float* __restrict__ A, const float* __restrict__ B,
                const float* __restrict__ bias, const float* __restrict__ kin,
                float* __restrict__ ewo, float* __restrict__ kko) {
    __shared__ float As[8][128], Bs[8][128];
    int tid = threadIdx.x, tx = tid & 15, ty = tid >> 4;
    int bx = blockIdx.x, by = blockIdx.y;
    float acc[8][8];
#pragma unroll
    for (int i = 0; i < 8; i++)
#pragma unroll
        for (int j = 0; j < 8; j++) acc[i][j] = 0.0f;
    int ar = tid >> 1, ac = (tid & 1) * 4, br = tid >> 5, bc = (tid & 31) * 4;
    for (int k0 = 0; k0 < 64; k0 += 8) {
        float4 av = *(const float4*)(A + (size_t)(by * 128 + ar) * 64 + k0 + ac);
        As[ac+0][ar] = av.x; As[ac+1][ar] = av.y; As[ac+2][ar] = av.z; As[ac+3][ar] = av.w;
        *(float4*)&Bs[br][bc] = *(const float4*)(B + (size_t)(k0 + br) * 2048 + bx * 128 + bc);
        __syncthreads();
#pragma unroll
        for (int kk = 0; kk < 8; kk++) {
            float a[8], b[8];
#pragma unroll
            for (int i = 0; i < 8; i++) a[i] = As[kk][ty * 8 + i];
#pragma unroll
            for (int j = 0; j < 8; j++) b[j] = Bs[kk][tx * 8 + j];
#pragma unroll
            for (int i = 0; i < 8; i++)
#pragma unroll
                for (int j = 0; j < 8; j++) acc[i][j] += a[i] * b[j];
        }
        __syncthreads();
    }
    int row0 = by * 128 + ty * 8, col0 = bx * 128 + tx * 8;
#pragma unroll
    for (int i = 0; i < 8; i++) {
        int row = row0 + i;
#pragma unroll
        for (int j = 0; j < 8; j++) {
            int col = col0 + j;
            float dec = acc[i][j] + bias[col];
            float lw = fmaxf(-expf(dec), -5.0f);
            float ew = expf(lw);
            size_t oidx = (size_t)row * 2048 + col;
            ewo[oidx] = ew;
            float kvv = kin[(size_t)row * 512 + (col >> 8) * 64 + (col & 63)];
            kko[oidx] = kvv * (1.0f - ew);
        }
    }
}

// ---------------- scan: prefetch + deferred reduce; og = (o*g) bf16 hi/lo --
__global__ __launch_bounds__(256)
void scan_kernel(const float* __restrict__ r, const float* __restrict__ kk,
                 const float* __restrict__ ew, const float* __restrict__ v,
                 const unsigned char* __restrict__ ns,
                 const float* __restrict__ state, const float* __restrict__ g,
                 __nv_bfloat16* __restrict__ ogh, __nv_bfloat16* __restrict__ ogl,
                 float* __restrict__ sfin) {
    int h = blockIdx.y, vs = blockIdx.x * 16;
    int tid = threadIdx.x, vl = tid >> 4, kg = tid & 15;
    int vcol = vs + vl, hv4 = (h >> 2) * 64;

    float s[4];
#pragma unroll
    for (int i = 0; i < 4; i++)
        s[i] = state[2048 + h * 4096 + (kg * 4 + i) * 64 + vcol];

    __shared__ float rs[2][64], ks[2][64], ws[2][64], vsd[2][16];
    __shared__ float pob[2][16][16];

    float reg = 0.0f;
    {
        size_t base = (size_t)h * 64;
        if (tid < 64)       reg = r[base + tid];
        else if (tid < 128) reg = kk[base + tid - 64];
        else if (tid < 192) reg = ew[base + tid - 128];
        else if (tid < 208) reg = v[hv4 + vs + tid - 192];
    }
    unsigned char nsr = ns[0];

    for (int t = 0; t < Tn; t++) {
        int b = t & 1;
        if (tid < 64)       rs[b][tid] = reg;
        else if (tid < 128) ks[b][tid - 64] = reg;
        else if (tid < 192) ws[b][tid - 128] = reg;
        else if (tid < 208) vsd[b][tid - 192] = reg;
        __syncthreads();

        unsigned char nsn = 0;
        if (t + 1 < Tn) {
            size_t base = (size_t)(t + 1) * 2048 + h * 64;
            if (tid < 64)       reg = r[base + tid];
            else if (tid < 128) reg = kk[base + tid - 64];
            else if (tid < 192) reg = ew[base + tid - 128];
            else if (tid < 208) reg = v[(size_t)(t + 1) * 512 + hv4 + vs + tid - 192];
            nsn = ns[t + 1];
        }

        if (t > 0 && kg == 0) {
            float acc = 0.0f;
#pragma unroll
            for (int i = 0; i < 16; i++) acc += pob[1 - b][i][vl];
            size_t ob = (size_t)(t - 1) * 2048 + h * 64 + vcol;
            float val = acc * g[ob];
            __nv_bfloat16 hh = __float2bfloat16(val);
            ogh[ob] = hh;
            ogl[ob] = __float2bfloat16(val - __bfloat162float(hh));
        }

        if (nsr) { s[0] = 0.f; s[1] = 0.f; s[2] = 0.f; s[3] = 0.f; }
        float vv = vsd[b][vl];
        float po = 0.0f;
#pragma unroll
        for (int i = 0; i < 4; i++) {
            int krow = kg * 4 + i;
            s[i] = s[i] * ws[b][krow] + ks[b][krow] * vv;
            po += rs[b][krow] * s[i];
        }
        pob[b][kg][vl] = po;
        nsr = nsn;
    }
    __syncthreads();
    if (kg == 0) {
        float acc = 0.0f;
#pragma unroll
        for (int i = 0; i < 16; i++) acc += pob[1][i][vl];
        size_t ob = (size_t)(Tn - 1) * 2048 + h * 64 + vcol;
        float val = acc * g[ob];
        __nv_bfloat16 hh = __float2bfloat16(val);
        ogh[ob] = hh;
        ogl[ob] = __float2bfloat16(val - __bfloat162float(hh));
    }
#pragma unroll
    for (int i = 0; i < 4; i++)
        sfin[h * 4096 + (kg * 4 + i) * 64 + vcol] = s[i];
}

// ---------------- tail ----------------
__global__ void tail_kernel(const float* __restrict__ x, const int* __restrict__ lenp,
                            const float* __restrict__ sfin, float* __restrict__ out) {
    int idx = blockIdx.x * blockDim.x + threadIdx.x;
    if (idx >= 65 * 2048) return;
    int len = *lenp;
    out[TC + idx] = (idx < 2048) ? x[(size_t)(len - 1) * 2048 + idx] : sfin[idx - 2048];
}

// ---------------------------------------------------------------------------
extern "C" void kernel_launch(void* const* d_in, const int* in_sizes, int n_in,
                              void* d_out, int out_size) {
    (void)in_sizes; (void)n_in;
    const float* x     = (const float*)d_in[0];
    const float* state = (const float*)d_in[1];
    const unsigned char* ns = (const unsigned char*)d_in[2];
    const int* lenp    = (const int*)d_in[3];
    const float* tmx   = (const float*)d_in[4];
    const float* tmr   = (const float*)d_in[5];
    const float* tmk   = (const float*)d_in[6];
    const float* tmv   = (const float*)d_in[7];
    const float* tmw   = (const float*)d_in[8];
    const float* tmg   = (const float*)d_in[9];
    const float* w1    = (const float*)d_in[10];
    const float* w2    = (const float*)d_in[11];
    const float* tdec  = (const float*)d_in[12];
    const float* tdw1  = (const float*)d_in[13];
    const float* tdw2  = (const float*)d_in[14];
    const float* Wq    = (const float*)d_in[15];
    const float* Wk    = (const float*)d_in[16];
    const float* Wv    = (const float*)d_in[17];
    const float* Wg    = (const float*)d_in[18];
    const float* Wo    = (const float*)d_in[19];
    float* out = (float*)d_out;

    float* S = nullptr;
    cudaGetSymbolAddress((void**)&S, g_scratch);
    auto bp = [&](size_t off) { return (__nv_bfloat16*)(S + off); };

    cudaFuncSetAttribute(hm_gemm, cudaFuncAttributeMaxDynamicSharedMemorySize, HG_SMEM);

    // 1. prep
    prep_kernel<<<(unsigned)((TC + 255) / 256), 256>>>(
        x, state, ns, tmx, tmr, tmk, tmv, tmw, tmg,
        S + OFF_SX, bp(OFF_XXH), bp(OFF_XXL), S + OFF_MAA);

    // 2. weight transpose + split
    tsplit_kernel<<<dim3(64, 64), dim3(32, 8)>>>(Wq, bp(OFF_WQH), bp(OFF_WQL), 2048);
    tsplit_kernel<<<dim3(64, 64), dim3(32, 8)>>>(Wg, bp(OFF_WGH), bp(OFF_WGL), 2048);
    tsplit_kernel<<<dim3(64, 64), dim3(32, 8)>>>(Wo, bp(OFF_WOH), bp(OFF_WOL), 2048);
    tsplit_kernel<<<dim3(16, 64), dim3(32, 8)>>>(Wk, bp(OFF_WKH), bp(OFF_WKL), 512);
    tsplit_kernel<<<dim3(16, 64), dim3(32, 8)>>>(Wv, bp(OFF_WVH), bp(OFF_WVL), 512);
    tsplit_kernel<<<dim3(5,  64), dim3(32, 8)>>>(w1, bp(OFF_W1H), bp(OFF_W1L), 160);
    tsplit_kernel<<<dim3(2,  64), dim3(32, 8)>>>(tdw1, bp(OFF_TDH), bp(OFF_TDL), 64);

    // 3. mbuf = tanh(xxx @ w1)  [T,160]
    hm_gemm<<<dim3(2, 16, 1), 256, HG_SMEM>>>(
        bp(OFF_XXH), bp(OFF_XXL), bp(OFF_W1H), bp(OFF_W1L), S + OFF_MBUF, 160, 160, 1,
        bp(OFF_XXH), bp(OFF_XXL), bp(OFF_W1H), bp(OFF_W1L), S + OFF_MBUF, 160, 160, 1);

    // 4. xb branches (K=32) -> bf16 hi/lo
    gemm_branch<<<dim3(16, 16, 5), 256>>>(S + OFF_MBUF, w2, x, S + OFF_SX,
                                          S + OFF_MAA, bp(OFF_XBH), bp(OFF_XBL));

    // 5. r = xr@Wq (plain) and g = sigmoid(xg@Wg), one dual launch
    hm_gemm<<<dim3(16, 16, 2), 256, HG_SMEM>>>(
        bp(OFF_XBH), bp(OFF_XBL), bp(OFF_WQH), bp(OFF_WQL), S + OFF_R, 2048, 2048, 0,
        bp(OFF_XBH) + 4 * TC, bp(OFF_XBL) + 4 * TC, bp(OFF_WGH), bp(OFF_WGL), S + OFF_G, 2048, 2048, 2);

    // 6. k and v, one dual launch
    hm_gemm<<<dim3(4, 16, 2), 256, HG_SMEM>>>(
        bp(OFF_XBH) + TC, bp(OFF_XBL) + TC, bp(OFF_WKH), bp(OFF_WKL), S + OFF_KR, 512, 512, 0,
        bp(OFF_XBH) + 2 * TC, bp(OFF_XBL) + 2 * TC, bp(OFF_WVH), bp(OFF_WVL), S + OFF_V, 512, 512, 0);

    // 7. d1 = tanh(xw @ tdw1) [T,64]; decay epilogue
    hm_gemm<<<dim3(1, 16, 1), 256, HG_SMEM>>>(
        bp(OFF_XBH) + 3 * TC, bp(OFF_XBL) + 3 * TC, bp(OFF_TDH), bp(OFF_TDL), S + OFF_D1, 64, 64, 1,
        bp(OFF_XBH) + 3 * TC, bp(OFF_XBL) + 3 * TC, bp(OFF_TDH), bp(OFF_TDL), S + OFF_D1, 64, 64, 1);
    gemm_decay<<<dim3(16, 16), 256>>>(S + OFF_D1, tdw2, tdec, S + OFF_KR,
                                      S + OFF_EW, S + OFF_KK);

    // 8. scan (fuses g-gate, emits og bf16 hi/lo)
    scan_kernel<<<dim3(4, 32), 256>>>(S + OFF_R, S + OFF_KK, S + OFF_EW, S + OFF_V,
                                      ns, state, S + OFF_G,
                                      bp(OFF_OGH), bp(OFF_OGL), S + OFF_SF);

    // 9. out = og @ Wo
    hm_gemm<<<dim3(16, 16, 1), 256, HG_SMEM>>>(
        bp(OFF_OGH), bp(OFF_OGL), bp(OFF_WOH), bp(OFF_WOL), out, 2048, 2048, 0,
        bp(OFF_OGH), bp(OFF_OGL), bp(OFF_WOH), bp(OFF_WOL), out, 2048, 2048, 0);

    // 10. new_state
    if ((size_t)out_size >= TC + 65 * 2048) {
        tail_kernel<<<(65 * 2048 + 255) / 256, 256>>>(x, lenp, S + OFF_SF, out);
    }
}